// round 2
// baseline (speedup 1.0000x reference)
#include <cuda_runtime.h>
#include <cuda_fp16.h>
#include <mma.h>
#include <cstdint>
#include <math.h>

using namespace nvcuda;

#define B_    32
#define V_    32000
#define EMB_  512
#define H_    1024
#define T_    100
#define KG    2048      // EMB + ZD + H
#define GROWS 4096      // 4*H
#define NCH   16
#define VCH   (V_ / NCH)   // 2000

// ---------------- static device state ----------------
__device__ __align__(128) half  g_wc_hi[GROWS * KG];        // 16.8 MB
__device__ __align__(128) half  g_wc_lo[GROWS * KG];        // 16.8 MB
__device__ __align__(128) half  g_wo[(size_t)V_ * H_];      // 65.5 MB
__device__ __align__(128) half  g_x_hi[KG * B_];            // [k][b]
__device__ __align__(128) half  g_x_lo[KG * B_];
__device__ __align__(128) float g_gates[GROWS * B_];        // [row][b]
__device__ __align__(128) float g_logits[B_ * V_];          // [b][v]
__device__ __align__(128) float g_c[H_ * B_];               // [hid][b]
__device__ __align__(128) float g_hf[B_ * H_];              // [b][hid] fp32 h for exact dots
__device__ int    g_s[B_];
__device__ float4 g_cA[B_ * NCH];   // (chunk maxl, chunk sumexp, cand1 val, cand1 idx-bits)
__device__ float2 g_cB[B_ * NCH];   // (cand2 val, cand2 idx-bits)
__device__ float  g_maxl[B_], g_sum[B_];

// ---------------- threefry2x32 (exact JAX) ----------------
__host__ __device__ inline void tf2x32(uint32_t k0, uint32_t k1, uint32_t x0, uint32_t x1,
                                       uint32_t &o0, uint32_t &o1) {
  uint32_t ks2 = k0 ^ k1 ^ 0x1BD11BDAu;
  x0 += k0; x1 += k1;
#define TF_R(r) do { x0 += x1; x1 = (x1 << (r)) | (x1 >> (32 - (r))); x1 ^= x0; } while (0)
  TF_R(13); TF_R(15); TF_R(26); TF_R(6);
  x0 += k1;  x1 += ks2 + 1u;
  TF_R(17); TF_R(29); TF_R(16); TF_R(24);
  x0 += ks2; x1 += k0 + 2u;
  TF_R(13); TF_R(15); TF_R(26); TF_R(6);
  x0 += k0;  x1 += k1 + 3u;
  TF_R(17); TF_R(29); TF_R(16); TF_R(24);
  x0 += k1;  x1 += ks2 + 4u;
  TF_R(13); TF_R(15); TF_R(26); TF_R(6);
  x0 += ks2; x1 += k0 + 5u;
#undef TF_R
  o0 = x0; o1 = x1;
}

// partitionable-mode 32-bit random bits for flat index i: xor of both threefry outputs
__device__ __forceinline__ uint32_t jax_bits(uint32_t k0, uint32_t k1, uint32_t i) {
  uint32_t a, b;
  tf2x32(k0, k1, 0u, i, a, b);
  return a ^ b;
}

__device__ __forceinline__ float gumbel_bits(uint32_t bits) {
  float u = __uint_as_float((bits >> 9) | 0x3f800000u) - 1.0f;   // [0,1)
  const float tiny = 1.17549435e-38f;
  float val = fmaxf(tiny, u * (1.0f - tiny) + tiny);
  return -logf(-logf(val));
}

__device__ __forceinline__ float gumbel_of(uint32_t k0, uint32_t k1, uint32_t i) {
  return gumbel_bits(jax_bits(k0, k1, i));
}

__device__ __forceinline__ float sigm(float x) { return 1.0f / (1.0f + expf(-x)); }

// ---------------- conversion / init ----------------
__global__ void k_conv_comb(const float* __restrict__ w_ih, const float* __restrict__ w_hh) {
  for (int i = blockIdx.x * blockDim.x + threadIdx.x; i < GROWS * KG; i += gridDim.x * blockDim.x) {
    int r = i >> 11, k = i & 2047;
    float v = (k < 1024) ? w_ih[r * 1024 + k] : w_hh[r * 1024 + (k - 1024)];
    half hi = __float2half(v);
    g_wc_hi[i] = hi;
    g_wc_lo[i] = __float2half(v - __half2float(hi));
  }
}
__global__ void k_conv_wout(const float* __restrict__ w) {
  for (size_t i = blockIdx.x * blockDim.x + threadIdx.x; i < (size_t)V_ * H_;
       i += (size_t)gridDim.x * blockDim.x)
    g_wo[i] = __float2half(w[i]);
}
__global__ void k_init(const float* __restrict__ z, const int* __restrict__ sid) {
  int idx = blockIdx.x * blockDim.x + threadIdx.x;
  if (idx < H_ * B_) {
    g_c[idx] = 0.0f;
    g_x_hi[H_ * B_ + idx] = __float2half(0.0f);   // h rows 1024..2047
    g_x_lo[H_ * B_ + idx] = __float2half(0.0f);
    int b = idx & 31, hid = idx >> 5;
    g_hf[b * H_ + hid] = 0.0f;
  }
  if (idx < EMB_ * B_) {                           // z rows 512..1023 (static)
    int b = idx & 31, k = idx >> 5;
    float v = z[b * EMB_ + k];
    half hi = __float2half(v);
    g_x_hi[(EMB_ + k) * B_ + b] = hi;
    g_x_lo[(EMB_ + k) * B_ + b] = __float2half(v - __half2float(hi));
  }
  if (idx < B_) g_s[idx] = sid ? sid[0] : 0;
}

// ---------------- per-step kernels ----------------
__global__ void k_embed(const float* __restrict__ emb) {
  int idx = blockIdx.x * blockDim.x + threadIdx.x;
  if (idx >= EMB_ * B_) return;
  int b = idx & 31, k = idx >> 5;
  float v = emb[g_s[b] * EMB_ + k];
  half hi = __float2half(v);
  g_x_hi[k * B_ + b] = hi;
  g_x_lo[k * B_ + b] = __float2half(v - __half2float(hi));
}

// gates = (Whi+Wlo)(xhi+xlo) ~ Whi*xhi + Wlo*xhi + Whi*xlo.  grid 128, block 128.
__global__ void k_gates() {
  int warp = threadIdx.x >> 5;
  int row0 = (blockIdx.x * 4 + warp) * 8;
  wmma::fragment<wmma::matrix_a, 8, 32, 16, half, wmma::row_major> fa;
  wmma::fragment<wmma::matrix_b, 8, 32, 16, half, wmma::row_major> fb;
  wmma::fragment<wmma::accumulator, 8, 32, 16, float> fc;
  wmma::fill_fragment(fc, 0.0f);
  const half* A[3] = { g_wc_hi + (size_t)row0 * KG, g_wc_lo + (size_t)row0 * KG,
                       g_wc_hi + (size_t)row0 * KG };
  const half* Bm[3] = { g_x_hi, g_x_hi, g_x_lo };
  for (int p = 0; p < 3; ++p) {
#pragma unroll 4
    for (int k = 0; k < KG; k += 16) {
      wmma::load_matrix_sync(fa, A[p] + k, KG);
      wmma::load_matrix_sync(fb, Bm[p] + k * B_, B_);
      wmma::mma_sync(fc, fa, fb, fc);
    }
  }
  wmma::store_matrix_sync(g_gates + row0 * B_, fc, B_, wmma::mem_row_major);
}

__global__ void k_cell(const float* __restrict__ bias) {
  int idx = blockIdx.x * blockDim.x + threadIdx.x;
  if (idx >= H_ * B_) return;
  int b = idx & 31, hid = idx >> 5;
  float ig = g_gates[hid * B_ + b]            + bias[hid];
  float fg = g_gates[(H_ + hid) * B_ + b]     + bias[H_ + hid];
  float gg = g_gates[(2 * H_ + hid) * B_ + b] + bias[2 * H_ + hid];
  float og = g_gates[(3 * H_ + hid) * B_ + b] + bias[3 * H_ + hid];
  float c  = g_c[idx];
  float cn = sigm(fg) * c + sigm(ig) * tanhf(gg);
  float hn = sigm(og) * tanhf(cn);
  g_c[idx] = cn;
  g_hf[b * H_ + hid] = hn;
  half hi = __float2half(hn);
  g_x_hi[(H_ + hid) * B_ + b] = hi;
  g_x_lo[(H_ + hid) * B_ + b] = __float2half(hn - __half2float(hi));
}

// logits = Wout_fp16 @ h_fp16.  grid 500, block 256.
__global__ void k_logits() {
  int warp = threadIdx.x >> 5;
  int row0 = (blockIdx.x * 8 + warp) * 8;
  wmma::fragment<wmma::matrix_a, 8, 32, 16, half, wmma::row_major> fa;
  wmma::fragment<wmma::matrix_b, 8, 32, 16, half, wmma::row_major> fb;
  wmma::fragment<wmma::accumulator, 8, 32, 16, float> fc;
  wmma::fill_fragment(fc, 0.0f);
  const half* arow = g_wo + (size_t)row0 * H_;
#pragma unroll 4
  for (int k = 0; k < H_; k += 16) {
    wmma::load_matrix_sync(fa, arow + k, H_);
    wmma::load_matrix_sync(fb, g_x_hi + (H_ + k) * B_, B_);
    wmma::mma_sync(fc, fa, fb, fc);
  }
  wmma::store_matrix_sync(g_logits + row0, fc, V_, wmma::mem_col_major);  // -> [b][v]
}

// per (chunk, b): chunk max, chunk sumexp, chunk top-2 of (l+gumbel).
__global__ void k_sample_part(const float* __restrict__ bout, uint32_t k0, uint32_t k1) {
  int chunk = blockIdx.x, b = blockIdx.y, tid = threadIdx.x;
  int vbeg = chunk * VCH, vend = vbeg + VCH;
  float m = -INFINITY, v1 = -INFINITY, v2 = -INFINITY;
  int i1 = 0x7fffffff, i2 = 0x7fffffff;
  for (int v = vbeg + tid; v < vend; v += 256) {
    float l = g_logits[b * V_ + v] + bout[v];
    m = fmaxf(m, l);
    float tv = l + gumbel_of(k0, k1, (uint32_t)(b * V_ + v));
    if (tv > v1 || (tv == v1 && v < i1)) { v2 = v1; i2 = i1; v1 = tv; i1 = v; }
    else if (tv > v2 || (tv == v2 && v < i2)) { v2 = tv; i2 = v; }
  }
  __shared__ float sm[256], s1[256], s2[256];
  __shared__ int   t1[256], t2[256];
  sm[tid] = m; s1[tid] = v1; s2[tid] = v2; t1[tid] = i1; t2[tid] = i2;
  __syncthreads();
  for (int off = 128; off; off >>= 1) {
    if (tid < off) {
      sm[tid] = fmaxf(sm[tid], sm[tid + off]);
      float b1 = s1[tid + off], b2 = s2[tid + off];
      int   j1 = t1[tid + off], j2 = t2[tid + off];
      float a1 = s1[tid], a2 = s2[tid];
      int   x1 = t1[tid], x2 = t2[tid];
      float n1, n2; int m1, m2;
      bool bf = (b1 > a1) || (b1 == a1 && j1 < x1);
      if (bf) { n1 = b1; m1 = j1; bool tk = (a1 > b2) || (a1 == b2 && x1 < j2);
                n2 = tk ? a1 : b2; m2 = tk ? x1 : j2; }
      else    { n1 = a1; m1 = x1; bool tk = (b1 > a2) || (b1 == a2 && j1 < x2);
                n2 = tk ? b1 : a2; m2 = tk ? j1 : x2; }
      s1[tid] = n1; s2[tid] = n2; t1[tid] = m1; t2[tid] = m2;
    }
    __syncthreads();
  }
  float cm = sm[0];
  __syncthreads();
  float su = 0.0f;
  for (int v = vbeg + tid; v < vend; v += 256)
    su += expf(g_logits[b * V_ + v] + bout[v] - cm);
  sm[tid] = su; __syncthreads();
  for (int off = 128; off; off >>= 1) { if (tid < off) sm[tid] += sm[tid + off]; __syncthreads(); }
  if (tid == 0) {
    g_cA[b * NCH + chunk] = make_float4(cm, sm[0], s1[0], __int_as_float(t1[0]));
    g_cB[b * NCH + chunk] = make_float2(s2[0], __int_as_float(t2[0]));
  }
}

// per b: global max/sumexp; exact (double) recompute of 32 candidates; pick winner.
__global__ void k_finalize(const float* __restrict__ wout, const float* __restrict__ bout,
                           float* outS, int t, uint32_t k0, uint32_t k1) {
  int b = blockIdx.x, tid = threadIdx.x, warp = tid >> 5, lane = tid & 31;
  __shared__ float sm, ssum;
  __shared__ double cval[2 * NCH];
  __shared__ int    cidx[2 * NCH];
  if (warp == 0) {
    float4 a = (lane < NCH) ? g_cA[b * NCH + lane] : make_float4(-INFINITY, 0.f, 0.f, 0.f);
    float m = a.x;
    for (int o = 16; o; o >>= 1) m = fmaxf(m, __shfl_xor_sync(0xffffffffu, m, o));
    float s = (lane < NCH) ? a.y * expf(a.x - m) : 0.0f;
    for (int o = 16; o; o >>= 1) s += __shfl_xor_sync(0xffffffffu, s, o);
    if (lane == 0) { sm = m; ssum = s; }
  }
  __syncthreads();
  for (int ci = warp; ci < 2 * NCH; ci += 8) {
    int chunk = ci & (NCH - 1);
    bool second = ci >= NCH;
    int v = second ? __float_as_int(g_cB[b * NCH + chunk].y)
                   : __float_as_int(g_cA[b * NCH + chunk].w);
    const float* wr = wout + (size_t)v * H_;
    const float* hr = g_hf + b * H_;
    double acc = 0.0;
    for (int j = lane; j < H_; j += 32) acc += (double)wr[j] * (double)hr[j];
    for (int o = 16; o; o >>= 1) acc += __shfl_down_sync(0xffffffffu, acc, o);
    if (lane == 0) {
      cval[ci] = acc + (double)bout[v] + (double)gumbel_of(k0, k1, (uint32_t)(b * V_ + v));
      cidx[ci] = v;
    }
  }
  __syncthreads();
  if (tid == 0) {
    double bv = -1e300; int bi = 0x7fffffff;
    for (int ci = 0; ci < 2 * NCH; ci++)
      if (cval[ci] > bv || (cval[ci] == bv && cidx[ci] < bi)) { bv = cval[ci]; bi = cidx[ci]; }
    g_s[b] = bi;
    g_maxl[b] = sm;
    g_sum[b] = ssum;
    if (outS) outS[b * T_ + t] = (float)bi;
  }
}

__global__ void k_write_p(float* __restrict__ outP, const float* __restrict__ bout, int t) {
  int idx = blockIdx.x * blockDim.x + threadIdx.x;
  if (idx >= B_ * V_) return;
  int b = idx / V_, v = idx - b * V_;
  float p = expf(g_logits[idx] + bout[v] - g_maxl[b]) / g_sum[b];
  outP[((size_t)b * T_ + t) * V_ + v] = p;
}

// ---------------- host ----------------
extern "C" void kernel_launch(void* const* d_in, const int* in_sizes, int n_in,
                              void* d_out, int out_size) {
  const float* z     = (const float*)d_in[0];
  const float* emb   = (const float*)d_in[1];
  const float* w_ih  = (const float*)d_in[2];
  const float* w_hh  = (const float*)d_in[3];
  const float* bias  = (const float*)d_in[4];
  const float* w_out = (const float*)d_in[5];
  const float* b_out = (const float*)d_in[6];
  const int*   sid   = (n_in > 7) ? (const int*)d_in[7] : nullptr;

  float* out  = (float*)d_out;
  float* outS = out;
  float* outP = out + B_ * T_;
  if (out_size == B_ * T_ * V_) { outS = nullptr; outP = out; }

  k_conv_comb<<<512, 256>>>(w_ih, w_hh);
  k_conv_wout<<<2048, 256>>>(w_out);
  k_init<<<(H_ * B_ + 255) / 256, 256>>>(z, sid);

  for (int t = 0; t < T_; ++t) {
    uint32_t fk0, fk1;
    tf2x32(0u, 42u, 0u, (uint32_t)t, fk0, fk1);   // fold_in(key(42), t)
    k_embed<<<(EMB_ * B_ + 255) / 256, 256>>>(emb);
    k_gates<<<128, 128>>>();
    k_cell<<<(H_ * B_ + 255) / 256, 256>>>(bias);
    k_logits<<<V_ / 64, 256>>>();
    dim3 gs(NCH, B_);
    k_sample_part<<<gs, 256>>>(b_out, fk0, fk1);
    k_finalize<<<B_, 256>>>(w_out, b_out, outS, t, fk0, fk1);
    k_write_p<<<(B_ * V_ + 255) / 256, 256>>>(outP, b_out, t);
  }
}

// round 3
// speedup vs baseline: 1.8784x; 1.8784x over previous
#include <cuda_runtime.h>
#include <cuda_fp16.h>
#include <mma.h>
#include <cstdint>
#include <math.h>

using namespace nvcuda;

#define B_    32
#define V_    32000
#define EMB_  512
#define H_    1024
#define T_    100
#define KG    2048      // EMB + ZD + H
#define GROWS 4096      // 4*H
#define NCH   16
#define VCH   (V_ / NCH)   // 2000
#define KSPL  8         // split-K for gates GEMM (virtual K = 6144)
#define RB    128       // rows per GEMM block
#define KC    64        // k per chunk

// ---------------- static device state ----------------
__device__ __align__(128) half  g_wc_hi[GROWS * KG];        // 16.8 MB
__device__ __align__(128) half  g_wc_lo[GROWS * KG];        // 16.8 MB
__device__ __align__(128) half  g_wo[(size_t)V_ * H_];      // 65.5 MB
__device__ __align__(128) half  g_x_hi[KG * B_];            // [k][b]
__device__ __align__(128) half  g_x_lo[KG * B_];
__device__ __align__(128) float g_part[(size_t)KSPL * GROWS * B_]; // 4 MB split-K partials
__device__ __align__(128) float g_logits[B_ * V_];          // [b][v]
__device__ __align__(128) float g_c[H_ * B_];               // [hid][b]
__device__ __align__(128) float g_hf[B_ * H_];              // [b][hid] fp32 h
__device__ int    g_s[B_];
__device__ float4 g_cA[B_ * NCH];   // (chunk max, unused, cand1 val, cand1 idx)
__device__ float2 g_cB[B_ * NCH];   // (cand2 val, cand2 idx)

// ---------------- threefry2x32 (exact JAX, partitionable mode) ----------------
__host__ __device__ inline void tf2x32(uint32_t k0, uint32_t k1, uint32_t x0, uint32_t x1,
                                       uint32_t &o0, uint32_t &o1) {
  uint32_t ks2 = k0 ^ k1 ^ 0x1BD11BDAu;
  x0 += k0; x1 += k1;
#define TF_R(r) do { x0 += x1; x1 = (x1 << (r)) | (x1 >> (32 - (r))); x1 ^= x0; } while (0)
  TF_R(13); TF_R(15); TF_R(26); TF_R(6);
  x0 += k1;  x1 += ks2 + 1u;
  TF_R(17); TF_R(29); TF_R(16); TF_R(24);
  x0 += ks2; x1 += k0 + 2u;
  TF_R(13); TF_R(15); TF_R(26); TF_R(6);
  x0 += k0;  x1 += k1 + 3u;
  TF_R(17); TF_R(29); TF_R(16); TF_R(24);
  x0 += k1;  x1 += ks2 + 4u;
  TF_R(13); TF_R(15); TF_R(26); TF_R(6);
  x0 += ks2; x1 += k0 + 5u;
#undef TF_R
  o0 = x0; o1 = x1;
}

__device__ __forceinline__ float gumbel_of(uint32_t k0, uint32_t k1, uint32_t i) {
  uint32_t a, b;
  tf2x32(k0, k1, 0u, i, a, b);
  uint32_t bits = a ^ b;
  float u = __uint_as_float((bits >> 9) | 0x3f800000u) - 1.0f;   // [0,1)
  const float tiny = 1.17549435e-38f;
  float val = fmaxf(tiny, u * (1.0f - tiny) + tiny);
  return -logf(-logf(val));
}

__device__ __forceinline__ float sigm(float x) { return 1.0f / (1.0f + expf(-x)); }

// ---------------- conversion / init ----------------
__global__ void k_conv_comb(const float* __restrict__ w_ih, const float* __restrict__ w_hh) {
  for (int i = blockIdx.x * blockDim.x + threadIdx.x; i < GROWS * KG; i += gridDim.x * blockDim.x) {
    int r = i >> 11, k = i & 2047;
    float v = (k < 1024) ? __ldcs(w_ih + r * 1024 + k) : __ldcs(w_hh + r * 1024 + (k - 1024));
    half hi = __float2half(v);
    g_wc_hi[i] = hi;
    g_wc_lo[i] = __float2half(v - __half2float(hi));
  }
}
__global__ void k_conv_wout(const float* __restrict__ w) {
  for (size_t i = blockIdx.x * blockDim.x + threadIdx.x; i < (size_t)V_ * H_;
       i += (size_t)gridDim.x * blockDim.x)
    g_wo[i] = __float2half(__ldcs(w + i));
}
__global__ void k_init(const float* __restrict__ z, const int* __restrict__ sid) {
  int idx = blockIdx.x * blockDim.x + threadIdx.x;
  if (idx < H_ * B_) {
    g_c[idx] = 0.0f;
    g_x_hi[H_ * B_ + idx] = __float2half(0.0f);
    g_x_lo[H_ * B_ + idx] = __float2half(0.0f);
    int b = idx & 31, hid = idx >> 5;
    g_hf[b * H_ + hid] = 0.0f;
  }
  if (idx < EMB_ * B_) {                           // z rows 512..1023 (static)
    int b = idx & 31, k = idx >> 5;
    float v = z[b * EMB_ + k];
    half hi = __float2half(v);
    g_x_hi[(EMB_ + k) * B_ + b] = hi;
    g_x_lo[(EMB_ + k) * B_ + b] = __float2half(v - __half2float(hi));
  }
  if (idx < B_) g_s[idx] = sid ? sid[0] : 0;
}
__global__ void k_embed0(const float* __restrict__ emb) {
  int idx = blockIdx.x * blockDim.x + threadIdx.x;
  if (idx >= EMB_ * B_) return;
  int b = idx & 31, k = idx >> 5;
  float v = emb[g_s[b] * EMB_ + k];
  half hi = __float2half(v);
  g_x_hi[k * B_ + b] = hi;
  g_x_lo[k * B_ + b] = __float2half(v - __half2float(hi));
}

// ---------------- gates GEMM: virtual K = 3*2048 (hi*xhi, lo*xhi, hi*xlo) -----
// grid (32, KSPL), block 256 (8 warps; warp -> 16 rows x 32 cols)
__global__ void k_gates() {
  __shared__ half As[2][RB * 72];
  const int row0 = blockIdx.x * RB;
  const int ks = blockIdx.y;
  const int tid = threadIdx.x, w = tid >> 5;
  const int vk0 = ks * (6144 / KSPL);
  const int NCHK = (6144 / KSPL) / KC;   // 12
  float4 rg[4];
  wmma::fragment<wmma::accumulator, 16, 16, 16, float> fc0, fc1;
  wmma::fill_fragment(fc0, 0.0f); wmma::fill_fragment(fc1, 0.0f);

  // prologue fetch
  {
    int vk = vk0, pass = vk >> 11, kk = vk & 2047;
    const half* W = (pass == 1) ? g_wc_lo : g_wc_hi;
#pragma unroll
    for (int i = 0; i < 4; i++) {
      int idx = tid + 256 * i, r = idx >> 3, c8 = idx & 7;
      rg[i] = *(const float4*)(W + (size_t)(row0 + r) * KG + kk + c8 * 8);
    }
#pragma unroll
    for (int i = 0; i < 4; i++) {
      int idx = tid + 256 * i, r = idx >> 3, c8 = idx & 7;
      *(float4*)(&As[0][r * 72 + c8 * 8]) = rg[i];
    }
  }
  __syncthreads();

  for (int c = 0; c < NCHK; c++) {
    int vk = vk0 + c * KC;
    if (c + 1 < NCHK) {
      int vk2 = vk + KC, pass2 = vk2 >> 11, kk2 = vk2 & 2047;
      const half* W = (pass2 == 1) ? g_wc_lo : g_wc_hi;
#pragma unroll
      for (int i = 0; i < 4; i++) {
        int idx = tid + 256 * i, r = idx >> 3, c8 = idx & 7;
        rg[i] = *(const float4*)(W + (size_t)(row0 + r) * KG + kk2 + c8 * 8);
      }
    }
    int pass = vk >> 11, kk = vk & 2047;
    const half* Bsrc = (pass == 2) ? g_x_lo : g_x_hi;
    wmma::fragment<wmma::matrix_a, 16, 16, 16, half, wmma::row_major> fa;
    wmma::fragment<wmma::matrix_b, 16, 16, 16, half, wmma::row_major> fb0, fb1;
#pragma unroll
    for (int k4 = 0; k4 < 4; k4++) {
      wmma::load_matrix_sync(fa, &As[c & 1][(w * 16) * 72 + k4 * 16], 72);
      wmma::load_matrix_sync(fb0, Bsrc + (kk + k4 * 16) * B_, B_);
      wmma::load_matrix_sync(fb1, Bsrc + (kk + k4 * 16) * B_ + 16, B_);
      wmma::mma_sync(fc0, fa, fb0, fc0);
      wmma::mma_sync(fc1, fa, fb1, fc1);
    }
    __syncthreads();
    if (c + 1 < NCHK) {
#pragma unroll
      for (int i = 0; i < 4; i++) {
        int idx = tid + 256 * i, r = idx >> 3, c8 = idx & 7;
        *(float4*)(&As[(c + 1) & 1][r * 72 + c8 * 8]) = rg[i];
      }
      __syncthreads();
    }
  }
  float* dst = g_part + ((size_t)ks * GROWS + row0 + w * 16) * B_;
  wmma::store_matrix_sync(dst, fc0, B_, wmma::mem_row_major);
  wmma::store_matrix_sync(dst + 16, fc1, B_, wmma::mem_row_major);
}

// ---------------- LSTM cell (+ split-K reduce) ----------------
__global__ void k_cell(const float* __restrict__ bias) {
  int idx = blockIdx.x * blockDim.x + threadIdx.x;
  if (idx >= H_ * B_) return;
  int b = idx & 31, hid = idx >> 5;
  float ig = 0.f, fg = 0.f, gg = 0.f, og = 0.f;
#pragma unroll
  for (int ks = 0; ks < KSPL; ks++) {
    const float* p = g_part + (size_t)ks * GROWS * B_;
    ig += p[hid * B_ + b];
    fg += p[(H_ + hid) * B_ + b];
    gg += p[(2 * H_ + hid) * B_ + b];
    og += p[(3 * H_ + hid) * B_ + b];
  }
  ig += bias[hid]; fg += bias[H_ + hid]; gg += bias[2 * H_ + hid]; og += bias[3 * H_ + hid];
  float c  = g_c[idx];
  float cn = sigm(fg) * c + sigm(ig) * tanhf(gg);
  float hn = sigm(og) * tanhf(cn);
  g_c[idx] = cn;
  g_hf[b * H_ + hid] = hn;
  half hi = __float2half(hn);
  g_x_hi[(H_ + hid) * B_ + b] = hi;
  g_x_lo[(H_ + hid) * B_ + b] = __float2half(hn - __half2float(hi));
}

// ---------------- logits GEMM: 32000x1024 @ 1024x32.  grid 250, block 256 ----
__global__ void k_logits() {
  __shared__ half As[2][RB * 72];
  const int row0 = blockIdx.x * RB;
  const int tid = threadIdx.x, w = tid >> 5;
  const half* Bsrc = g_x_hi + H_ * B_;   // h rows
  float4 rg[4];
  wmma::fragment<wmma::accumulator, 16, 16, 16, float> fc0, fc1;
  wmma::fill_fragment(fc0, 0.0f); wmma::fill_fragment(fc1, 0.0f);

  {
#pragma unroll
    for (int i = 0; i < 4; i++) {
      int idx = tid + 256 * i, r = idx >> 3, c8 = idx & 7;
      rg[i] = *(const float4*)(g_wo + (size_t)(row0 + r) * H_ + c8 * 8);
    }
#pragma unroll
    for (int i = 0; i < 4; i++) {
      int idx = tid + 256 * i, r = idx >> 3, c8 = idx & 7;
      *(float4*)(&As[0][r * 72 + c8 * 8]) = rg[i];
    }
  }
  __syncthreads();

  const int NCHK = H_ / KC;   // 16
  for (int c = 0; c < NCHK; c++) {
    int kk = c * KC;
    if (c + 1 < NCHK) {
#pragma unroll
      for (int i = 0; i < 4; i++) {
        int idx = tid + 256 * i, r = idx >> 3, c8 = idx & 7;
        rg[i] = *(const float4*)(g_wo + (size_t)(row0 + r) * H_ + kk + KC + c8 * 8);
      }
    }
    wmma::fragment<wmma::matrix_a, 16, 16, 16, half, wmma::row_major> fa;
    wmma::fragment<wmma::matrix_b, 16, 16, 16, half, wmma::row_major> fb0, fb1;
#pragma unroll
    for (int k4 = 0; k4 < 4; k4++) {
      wmma::load_matrix_sync(fa, &As[c & 1][(w * 16) * 72 + k4 * 16], 72);
      wmma::load_matrix_sync(fb0, Bsrc + (kk + k4 * 16) * B_, B_);
      wmma::load_matrix_sync(fb1, Bsrc + (kk + k4 * 16) * B_ + 16, B_);
      wmma::mma_sync(fc0, fa, fb0, fc0);
      wmma::mma_sync(fc1, fa, fb1, fc1);
    }
    __syncthreads();
    if (c + 1 < NCHK) {
#pragma unroll
      for (int i = 0; i < 4; i++) {
        int idx = tid + 256 * i, r = idx >> 3, c8 = idx & 7;
        *(float4*)(&As[(c + 1) & 1][r * 72 + c8 * 8]) = rg[i];
      }
      __syncthreads();
    }
  }
  float* dst = g_logits + row0 + w * 16;
  wmma::store_matrix_sync(dst, fc0, V_, wmma::mem_col_major);
  wmma::store_matrix_sync(dst + (size_t)16 * V_, fc1, V_, wmma::mem_col_major);
}

// ---------------- sampling pass 1: chunk max + top-2(l+gumbel).  grid (16,32) -
__global__ void k_sample_part(const float* __restrict__ bout, uint32_t k0, uint32_t k1) {
  int chunk = blockIdx.x, b = blockIdx.y, tid = threadIdx.x;
  int vbeg = chunk * VCH, vend = vbeg + VCH;
  float m = -INFINITY, v1 = -INFINITY, v2 = -INFINITY;
  int i1 = 0x7fffffff, i2 = 0x7fffffff;
  for (int v = vbeg + tid; v < vend; v += 256) {
    float l = g_logits[b * V_ + v] + bout[v];
    m = fmaxf(m, l);
    float tv = l + gumbel_of(k0, k1, (uint32_t)(b * V_ + v));
    if (tv > v1 || (tv == v1 && v < i1)) { v2 = v1; i2 = i1; v1 = tv; i1 = v; }
    else if (tv > v2 || (tv == v2 && v < i2)) { v2 = tv; i2 = v; }
  }
  __shared__ float sm[256], s1[256], s2[256];
  __shared__ int   t1[256], t2[256];
  sm[tid] = m; s1[tid] = v1; s2[tid] = v2; t1[tid] = i1; t2[tid] = i2;
  __syncthreads();
  for (int off = 128; off; off >>= 1) {
    if (tid < off) {
      sm[tid] = fmaxf(sm[tid], sm[tid + off]);
      float b1 = s1[tid + off], b2 = s2[tid + off];
      int   j1 = t1[tid + off], j2 = t2[tid + off];
      float a1 = s1[tid], a2 = s2[tid];
      int   x1 = t1[tid], x2 = t2[tid];
      float n1, n2; int m1, m2;
      bool bf = (b1 > a1) || (b1 == a1 && j1 < x1);
      if (bf) { n1 = b1; m1 = j1; bool tk = (a1 > b2) || (a1 == b2 && x1 < j2);
                n2 = tk ? a1 : b2; m2 = tk ? x1 : j2; }
      else    { n1 = a1; m1 = x1; bool tk = (b1 > a2) || (b1 == a2 && j1 < x2);
                n2 = tk ? b1 : a2; m2 = tk ? j1 : x2; }
      s1[tid] = n1; s2[tid] = n2; t1[tid] = m1; t2[tid] = m2;
    }
    __syncthreads();
  }
  if (tid == 0) {
    g_cA[b * NCH + chunk] = make_float4(sm[0], 0.0f, s1[0], __int_as_float(t1[0]));
    g_cB[b * NCH + chunk] = make_float2(s2[0], __int_as_float(t2[0]));
  }
}

// ---------------- finalize: max/sumexp, exact candidate pick, p write, embed --
__global__ void k_finalize(const float* __restrict__ wout, const float* __restrict__ bout,
                           const float* __restrict__ emb,
                           float* outS, float* __restrict__ outP,
                           int t, uint32_t k0, uint32_t k1) {
  int b = blockIdx.x, tid = threadIdx.x, w = tid >> 5, lane = tid & 31;
  __shared__ float s_m, s_sum;
  __shared__ int   s_tok;
  __shared__ float red[256];
  __shared__ double cval[2 * NCH];
  __shared__ int    cidx[2 * NCH];
  if (w == 0) {
    float m = (lane < NCH) ? g_cA[b * NCH + lane].x : -INFINITY;
    for (int o = 16; o; o >>= 1) m = fmaxf(m, __shfl_xor_sync(0xffffffffu, m, o));
    if (lane == 0) s_m = m;
  }
  __syncthreads();
  float m = s_m;
  float s = 0.0f;
  for (int v = tid; v < V_; v += 256)
    s += expf(g_logits[b * V_ + v] + bout[v] - m);
  red[tid] = s; __syncthreads();
  for (int off = 128; off; off >>= 1) { if (tid < off) red[tid] += red[tid + off]; __syncthreads(); }
  if (tid == 0) s_sum = red[0];
  // exact candidate recompute in double
  for (int ci = w; ci < 2 * NCH; ci += 8) {
    int chunk = ci & (NCH - 1);
    int v = (ci >= NCH) ? __float_as_int(g_cB[b * NCH + chunk].y)
                        : __float_as_int(g_cA[b * NCH + chunk].w);
    const float* wr = wout + (size_t)v * H_;
    const float* hr = g_hf + b * H_;
    double acc = 0.0;
    for (int j = lane; j < H_; j += 32) acc += (double)wr[j] * (double)hr[j];
    for (int o = 16; o; o >>= 1) acc += __shfl_down_sync(0xffffffffu, acc, o);
    if (lane == 0) {
      cval[ci] = acc + (double)bout[v] + (double)gumbel_of(k0, k1, (uint32_t)(b * V_ + v));
      cidx[ci] = v;
    }
  }
  __syncthreads();
  if (tid == 0) {
    double bv = -1e300; int bi = 0x7fffffff;
    for (int ci = 0; ci < 2 * NCH; ci++)
      if (cval[ci] > bv || (cval[ci] == bv && cidx[ci] < bi)) { bv = cval[ci]; bi = cidx[ci]; }
    s_tok = bi;
    g_s[b] = bi;
    if (outS) outS[b * T_ + t] = (float)bi;
  }
  __syncthreads();
  float invs = 1.0f / s_sum;
  float* op = outP + ((size_t)b * T_ + t) * V_;
  for (int v = tid; v < V_; v += 256)
    __stcs(op + v, expf(g_logits[b * V_ + v] + bout[v] - m) * invs);
  // embed next token for step t+1
  int tok = s_tok;
  for (int k = tid; k < EMB_; k += 256) {
    float val = emb[tok * EMB_ + k];
    half hi = __float2half(val);
    g_x_hi[k * B_ + b] = hi;
    g_x_lo[k * B_ + b] = __float2half(val - __half2float(hi));
  }
}

// ---------------- host ----------------
extern "C" void kernel_launch(void* const* d_in, const int* in_sizes, int n_in,
                              void* d_out, int out_size) {
  const float* z     = (const float*)d_in[0];
  const float* emb   = (const float*)d_in[1];
  const float* w_ih  = (const float*)d_in[2];
  const float* w_hh  = (const float*)d_in[3];
  const float* bias  = (const float*)d_in[4];
  const float* w_out = (const float*)d_in[5];
  const float* b_out = (const float*)d_in[6];
  const int*   sid   = (n_in > 7) ? (const int*)d_in[7] : nullptr;

  float* out  = (float*)d_out;
  float* outS = out;
  float* outP = out + B_ * T_;
  if (out_size == B_ * T_ * V_) { outS = nullptr; outP = out; }

  k_conv_comb<<<512, 256>>>(w_ih, w_hh);
  k_conv_wout<<<2048, 256>>>(w_out);
  k_init<<<(H_ * B_ + 255) / 256, 256>>>(z, sid);
  k_embed0<<<(EMB_ * B_ + 255) / 256, 256>>>(emb);

  for (int t = 0; t < T_; ++t) {
    uint32_t fk0, fk1;
    tf2x32(0u, 42u, 0u, (uint32_t)t, fk0, fk1);   // fold_in(key(42), t)
    k_gates<<<dim3(GROWS / RB, KSPL), 256>>>();
    k_cell<<<(H_ * B_ + 255) / 256, 256>>>(bias);
    k_logits<<<V_ / RB, 256>>>();
    k_sample_part<<<dim3(NCH, B_), 256>>>(b_out, fk0, fk1);
    k_finalize<<<B_, 256>>>(w_out, b_out, emb, outS, outP, t, fk0, fk1);
  }
}

// round 4
// speedup vs baseline: 2.7026x; 1.4388x over previous
#include <cuda_runtime.h>
#include <cuda_fp16.h>
#include <mma.h>
#include <cstdint>
#include <math.h>

using namespace nvcuda;

#define B_    32
#define V_    32000
#define EMB_  512
#define H_    1024
#define T_    100
#define KG    2048
#define GROWS 4096
#define NCH   16
#define VCH   (V_ / NCH)     // 2000
#define KSPL  8              // split-K for gates (virtual K = 4096)
#define RB    128
#define KC    32
#define NPB   16             // p-writer blocks per batch row in k_post

// ---------------- static device state ----------------
__device__ __align__(128) half  g_wc_hi[GROWS * KG];          // 16.8 MB
__device__ __align__(128) half  g_wc_lo[GROWS * KG];          // 16.8 MB
__device__ __align__(128) half  g_wo[(size_t)V_ * H_];        // 65.5 MB
__device__ __align__(128) half  g_x_hi[KG * B_];              // [k][b]
__device__ __align__(128) half  g_x_lo[KG * B_];
__device__ __align__(128) float g_part[(size_t)KSPL * GROWS * B_];
__device__ __align__(128) float g_logits[B_ * V_];            // [b][v]
__device__ __align__(128) float g_c[H_ * B_];
__device__ __align__(128) float g_hf[B_ * H_];                // [b][hid] fp32 h
__device__ int    g_s[B_];
__device__ float4 g_cA[B_ * NCH];   // (chunk max, chunk sum, cand1 val, cand1 idx)
__device__ float2 g_cB[B_ * NCH];   // (cand2 val, cand2 idx)

// ---------------- cp.async helpers ----------------
__device__ __forceinline__ void cp16(void* sdst, const void* gsrc) {
  uint32_t d = (uint32_t)__cvta_generic_to_shared(sdst);
  asm volatile("cp.async.cg.shared.global [%0], [%1], 16;\n" :: "r"(d), "l"(gsrc));
}
#define CP_COMMIT() asm volatile("cp.async.commit_group;\n" ::: "memory")
#define CP_WAIT(n)  asm volatile("cp.async.wait_group %0;\n" :: "n"(n) : "memory")

// ---------------- threefry2x32 (exact JAX, partitionable) ----------------
__host__ __device__ inline void tf2x32(uint32_t k0, uint32_t k1, uint32_t x0, uint32_t x1,
                                       uint32_t &o0, uint32_t &o1) {
  uint32_t ks2 = k0 ^ k1 ^ 0x1BD11BDAu;
  x0 += k0; x1 += k1;
#define TF_R(r) do { x0 += x1; x1 = (x1 << (r)) | (x1 >> (32 - (r))); x1 ^= x0; } while (0)
  TF_R(13); TF_R(15); TF_R(26); TF_R(6);
  x0 += k1;  x1 += ks2 + 1u;
  TF_R(17); TF_R(29); TF_R(16); TF_R(24);
  x0 += ks2; x1 += k0 + 2u;
  TF_R(13); TF_R(15); TF_R(26); TF_R(6);
  x0 += k0;  x1 += k1 + 3u;
  TF_R(17); TF_R(29); TF_R(16); TF_R(24);
  x0 += k1;  x1 += ks2 + 4u;
  TF_R(13); TF_R(15); TF_R(26); TF_R(6);
  x0 += ks2; x1 += k0 + 5u;
#undef TF_R
  o0 = x0; o1 = x1;
}

__device__ __forceinline__ float gumbel_of(uint32_t k0, uint32_t k1, uint32_t i) {
  uint32_t a, b;
  tf2x32(k0, k1, 0u, i, a, b);
  uint32_t bits = a ^ b;
  float u = __uint_as_float((bits >> 9) | 0x3f800000u) - 1.0f;
  const float tiny = 1.17549435e-38f;
  float val = fmaxf(tiny, u * (1.0f - tiny) + tiny);
  return -logf(-logf(val));
}

__device__ __forceinline__ float sigm(float x) { return 1.0f / (1.0f + expf(-x)); }

// ---------------- conversion / init ----------------
__global__ void k_conv_comb(const float* __restrict__ w_ih, const float* __restrict__ w_hh) {
  for (int i = blockIdx.x * blockDim.x + threadIdx.x; i < GROWS * KG; i += gridDim.x * blockDim.x) {
    int r = i >> 11, k = i & 2047;
    float v = (k < 1024) ? __ldcs(w_ih + r * 1024 + k) : __ldcs(w_hh + r * 1024 + (k - 1024));
    half hi = __float2half(v);
    g_wc_hi[i] = hi;
    g_wc_lo[i] = __float2half(v - __half2float(hi));
  }
}
__global__ void k_conv_wout(const float* __restrict__ w) {
  for (size_t i = blockIdx.x * blockDim.x + threadIdx.x; i < (size_t)V_ * H_;
       i += (size_t)gridDim.x * blockDim.x)
    g_wo[i] = __float2half(__ldcs(w + i));
}
__global__ void k_init(const float* __restrict__ z, const int* __restrict__ sid,
                       const float* __restrict__ emb) {
  int idx = blockIdx.x * blockDim.x + threadIdx.x;
  if (idx < H_ * B_) {
    g_c[idx] = 0.0f;
    g_x_hi[H_ * B_ + idx] = __float2half(0.0f);
    g_x_lo[H_ * B_ + idx] = __float2half(0.0f);
    int b = idx & 31, hid = idx >> 5;
    g_hf[b * H_ + hid] = 0.0f;
  }
  if (idx < EMB_ * B_) {                           // z rows 512..1023 (static)
    int b = idx & 31, k = idx >> 5;
    float v = z[b * EMB_ + k];
    half hi = __float2half(v);
    g_x_hi[(EMB_ + k) * B_ + b] = hi;
    g_x_lo[(EMB_ + k) * B_ + b] = __float2half(v - __half2float(hi));
    // token-0 embedding rows 0..511
    int tok = sid ? sid[0] : 0;
    float e = emb[tok * EMB_ + k];
    half ehi = __float2half(e);
    g_x_hi[k * B_ + b] = ehi;
    g_x_lo[k * B_ + b] = __float2half(e - __half2float(ehi));
  }
  if (idx < B_) g_s[idx] = sid ? sid[0] : 0;
}

// ---------------- gates GEMM (cp.async 3-stage) ----------------
// virtual K = 4096: [0,2048) = Whi chunk used vs BOTH xhi,xlo; [2048,4096) = Wlo vs xhi.
// grid (32, 8), block 256 (8 warps; warp -> 16 rows x 32 cols)
__global__ void k_gates() {
  __shared__ half As[3][RB * 40];
  __shared__ half Bh[3][KC * 40];
  __shared__ half Bl[3][KC * 40];
  const int row0 = blockIdx.x * RB;
  const int ks = blockIdx.y;
  const int tid = threadIdx.x, w = tid >> 5;
  const bool hiPhase = ks < 4;
  const half* Wsrc = hiPhase ? g_wc_hi : g_wc_lo;
  const int kk0 = (ks & 3) * 512;
  const int NCHK = 512 / KC;   // 16

  wmma::fragment<wmma::accumulator, 16, 16, 16, float> fc0, fc1;
  wmma::fill_fragment(fc0, 0.0f); wmma::fill_fragment(fc1, 0.0f);

  auto issue = [&](int c) {
    int s = c % 3, kk = kk0 + c * KC;
    // A: 128 rows x 32 halves = 512 x 16B
#pragma unroll
    for (int j = 0; j < 2; j++) {
      int idx = tid + 256 * j, r = idx >> 2, cc = idx & 3;
      cp16(&As[s][r * 40 + cc * 8], Wsrc + (size_t)(row0 + r) * KG + kk + cc * 8);
    }
    // B: 32 k-rows x 32 b = 128 x 16B
    if (tid < 128) {
      int r = tid >> 2, cc = tid & 3;
      cp16(&Bh[s][r * 40 + cc * 8], g_x_hi + (kk + r) * B_ + cc * 8);
      if (hiPhase)
        cp16(&Bl[s][r * 40 + cc * 8], g_x_lo + (kk + r) * B_ + cc * 8);
    }
    CP_COMMIT();
  };

  issue(0); issue(1); issue(2);

  for (int c = 0; c < NCHK; c++) {
    if (c + 3 < NCHK) { CP_WAIT(2); } else { CP_WAIT(0); }
    __syncthreads();
    int s = c % 3;
    wmma::fragment<wmma::matrix_a, 16, 16, 16, half, wmma::row_major> fa;
    wmma::fragment<wmma::matrix_b, 16, 16, 16, half, wmma::row_major> fb0, fb1;
#pragma unroll
    for (int k4 = 0; k4 < 2; k4++) {
      wmma::load_matrix_sync(fa, &As[s][(w * 16) * 40 + k4 * 16], 40);
      wmma::load_matrix_sync(fb0, &Bh[s][(k4 * 16) * 40 + 0], 40);
      wmma::load_matrix_sync(fb1, &Bh[s][(k4 * 16) * 40 + 16], 40);
      wmma::mma_sync(fc0, fa, fb0, fc0);
      wmma::mma_sync(fc1, fa, fb1, fc1);
      if (hiPhase) {
        wmma::load_matrix_sync(fb0, &Bl[s][(k4 * 16) * 40 + 0], 40);
        wmma::load_matrix_sync(fb1, &Bl[s][(k4 * 16) * 40 + 16], 40);
        wmma::mma_sync(fc0, fa, fb0, fc0);
        wmma::mma_sync(fc1, fa, fb1, fc1);
      }
    }
    __syncthreads();
    if (c + 3 < NCHK) issue(c + 3);
  }
  float* dst = g_part + ((size_t)ks * GROWS + row0 + w * 16) * B_;
  wmma::store_matrix_sync(dst, fc0, B_, wmma::mem_row_major);
  wmma::store_matrix_sync(dst + 16, fc1, B_, wmma::mem_row_major);
}

// ---------------- LSTM cell (+ split-K reduce) ----------------
__global__ void k_cell(const float* __restrict__ bias) {
  int idx = blockIdx.x * blockDim.x + threadIdx.x;
  if (idx >= H_ * B_) return;
  int b = idx & 31, hid = idx >> 5;
  float ig = 0.f, fg = 0.f, gg = 0.f, og = 0.f;
#pragma unroll
  for (int ks = 0; ks < KSPL; ks++) {
    const float* p = g_part + (size_t)ks * GROWS * B_;
    ig += p[hid * B_ + b];
    fg += p[(H_ + hid) * B_ + b];
    gg += p[(2 * H_ + hid) * B_ + b];
    og += p[(3 * H_ + hid) * B_ + b];
  }
  ig += bias[hid]; fg += bias[H_ + hid]; gg += bias[2 * H_ + hid]; og += bias[3 * H_ + hid];
  float c  = g_c[idx];
  float cn = sigm(fg) * c + sigm(ig) * tanhf(gg);
  float hn = sigm(og) * tanhf(cn);
  g_c[idx] = cn;
  g_hf[b * H_ + hid] = hn;
  half hi = __float2half(hn);
  g_x_hi[(H_ + hid) * B_ + b] = hi;
  g_x_lo[(H_ + hid) * B_ + b] = __float2half(hn - __half2float(hi));
}

// ---------------- logits GEMM (cp.async 3-stage).  grid 250, block 256 -------
__global__ void k_logits() {
  __shared__ half As[3][RB * 40];
  __shared__ half Bs[3][KC * 40];
  const int row0 = blockIdx.x * RB;
  const int tid = threadIdx.x, w = tid >> 5;
  const half* Bsrc = g_x_hi + H_ * B_;
  const int NCHK = H_ / KC;   // 32

  wmma::fragment<wmma::accumulator, 16, 16, 16, float> fc0, fc1;
  wmma::fill_fragment(fc0, 0.0f); wmma::fill_fragment(fc1, 0.0f);

  auto issue = [&](int c) {
    int s = c % 3, kk = c * KC;
#pragma unroll
    for (int j = 0; j < 2; j++) {
      int idx = tid + 256 * j, r = idx >> 2, cc = idx & 3;
      cp16(&As[s][r * 40 + cc * 8], g_wo + (size_t)(row0 + r) * H_ + kk + cc * 8);
    }
    if (tid < 128) {
      int r = tid >> 2, cc = tid & 3;
      cp16(&Bs[s][r * 40 + cc * 8], Bsrc + (kk + r) * B_ + cc * 8);
    }
    CP_COMMIT();
  };

  issue(0); issue(1); issue(2);

  for (int c = 0; c < NCHK; c++) {
    if (c + 3 < NCHK) { CP_WAIT(2); } else { CP_WAIT(0); }
    __syncthreads();
    int s = c % 3;
    wmma::fragment<wmma::matrix_a, 16, 16, 16, half, wmma::row_major> fa;
    wmma::fragment<wmma::matrix_b, 16, 16, 16, half, wmma::row_major> fb0, fb1;
#pragma unroll
    for (int k4 = 0; k4 < 2; k4++) {
      wmma::load_matrix_sync(fa, &As[s][(w * 16) * 40 + k4 * 16], 40);
      wmma::load_matrix_sync(fb0, &Bs[s][(k4 * 16) * 40 + 0], 40);
      wmma::load_matrix_sync(fb1, &Bs[s][(k4 * 16) * 40 + 16], 40);
      wmma::mma_sync(fc0, fa, fb0, fc0);
      wmma::mma_sync(fc1, fa, fb1, fc1);
    }
    __syncthreads();
    if (c + 3 < NCHK) issue(c + 3);
  }
  float* dst = g_logits + row0 + w * 16;
  wmma::store_matrix_sync(dst, fc0, V_, wmma::mem_col_major);
  wmma::store_matrix_sync(dst + (size_t)16 * V_, fc1, V_, wmma::mem_col_major);
}

// ------- sampling pass: online max/sumexp + top-2(l+gumbel).  grid (16,32) ----
__global__ void k_sample_part(const float* __restrict__ bout, uint32_t k0, uint32_t k1) {
  int chunk = blockIdx.x, b = blockIdx.y, tid = threadIdx.x;
  int vbeg = chunk * VCH, vend = vbeg + VCH;
  float m = -INFINITY, s = 0.0f, v1 = -INFINITY, v2 = -INFINITY;
  int i1 = 0x7fffffff, i2 = 0x7fffffff;
  for (int v = vbeg + tid; v < vend; v += 256) {
    float l = g_logits[b * V_ + v] + bout[v];
    if (l > m) { s = s * expf(m - l) + 1.0f; m = l; } else s += expf(l - m);
    float tv = l + gumbel_of(k0, k1, (uint32_t)(b * V_ + v));
    if (tv > v1 || (tv == v1 && v < i1)) { v2 = v1; i2 = i1; v1 = tv; i1 = v; }
    else if (tv > v2 || (tv == v2 && v < i2)) { v2 = tv; i2 = v; }
  }
  __shared__ float sm[256], ss[256], s1[256], s2[256];
  __shared__ int   t1[256], t2[256];
  sm[tid] = m; ss[tid] = s; s1[tid] = v1; s2[tid] = v2; t1[tid] = i1; t2[tid] = i2;
  __syncthreads();
  for (int off = 128; off; off >>= 1) {
    if (tid < off) {
      float mA = sm[tid], mB = sm[tid + off];
      float M = fmaxf(mA, mB);
      sm[tid] = M;
      ss[tid] = ss[tid] * expf(mA - M) + ss[tid + off] * expf(mB - M);
      float b1 = s1[tid + off], b2 = s2[tid + off];
      int   j1 = t1[tid + off], j2 = t2[tid + off];
      float a1 = s1[tid], a2 = s2[tid];
      int   x1 = t1[tid], x2 = t2[tid];
      float n1, n2; int m1, m2;
      bool bf = (b1 > a1) || (b1 == a1 && j1 < x1);
      if (bf) { n1 = b1; m1 = j1; bool tk = (a1 > b2) || (a1 == b2 && x1 < j2);
                n2 = tk ? a1 : b2; m2 = tk ? x1 : j2; }
      else    { n1 = a1; m1 = x1; bool tk = (b1 > a2) || (b1 == a2 && j1 < x2);
                n2 = tk ? b1 : a2; m2 = tk ? j1 : x2; }
      s1[tid] = n1; s2[tid] = n2; t1[tid] = m1; t2[tid] = m2;
    }
    __syncthreads();
  }
  if (tid == 0) {
    g_cA[b * NCH + chunk] = make_float4(sm[0], ss[0], s1[0], __int_as_float(t1[0]));
    g_cB[b * NCH + chunk] = make_float2(s2[0], __int_as_float(t2[0]));
  }
}

// ---- post: p write (blocks 0..15) + token finalize/embed (block 16). grid (17,32)
__global__ void k_post(const float* __restrict__ wout, const float* __restrict__ bout,
                       const float* __restrict__ emb,
                       float* outS, float* __restrict__ outP,
                       int t, uint32_t k0, uint32_t k1) {
  int c = blockIdx.x, b = blockIdx.y, tid = threadIdx.x, w = tid >> 5, lane = tid & 31;
  __shared__ float s_m, s_inv;
  if (w == 0) {
    float4 a = (lane < NCH) ? g_cA[b * NCH + lane] : make_float4(-INFINITY, 0.f, 0.f, 0.f);
    float m = a.x;
    for (int o = 16; o; o >>= 1) m = fmaxf(m, __shfl_xor_sync(0xffffffffu, m, o));
    float su = (lane < NCH) ? a.y * expf(a.x - m) : 0.0f;
    for (int o = 16; o; o >>= 1) su += __shfl_xor_sync(0xffffffffu, su, o);
    if (lane == 0) { s_m = m; s_inv = 1.0f / su; }
  }
  __syncthreads();
  float m = s_m, inv = s_inv;

  if (c < NPB) {
    int vbeg = c * VCH;
    float* op = outP + ((size_t)b * T_ + t) * V_;
    for (int v = vbeg + tid; v < vbeg + VCH; v += 256)
      __stcs(op + v, expf(g_logits[b * V_ + v] + bout[v] - m) * inv);
    return;
  }

  // finalize block: exact candidate recompute in double
  __shared__ double cval[2 * NCH];
  __shared__ int    cidx[2 * NCH];
  __shared__ int    s_tok;
  for (int ci = w; ci < 2 * NCH; ci += 8) {
    int chunk = ci & (NCH - 1);
    int v = (ci >= NCH) ? __float_as_int(g_cB[b * NCH + chunk].y)
                        : __float_as_int(g_cA[b * NCH + chunk].w);
    const float* wr = wout + (size_t)v * H_;
    const float* hr = g_hf + b * H_;
    double acc = 0.0;
    for (int j = lane; j < H_; j += 32) acc += (double)wr[j] * (double)hr[j];
    for (int o = 16; o; o >>= 1) acc += __shfl_down_sync(0xffffffffu, acc, o);
    if (lane == 0) {
      cval[ci] = acc + (double)bout[v] + (double)gumbel_of(k0, k1, (uint32_t)(b * V_ + v));
      cidx[ci] = v;
    }
  }
  __syncthreads();
  if (tid == 0) {
    double bv = -1e300; int bi = 0x7fffffff;
    for (int ci = 0; ci < 2 * NCH; ci++)
      if (cval[ci] > bv || (cval[ci] == bv && cidx[ci] < bi)) { bv = cval[ci]; bi = cidx[ci]; }
    s_tok = bi;
    g_s[b] = bi;
    if (outS) outS[b * T_ + t] = (float)bi;
  }
  __syncthreads();
  int tok = s_tok;
  for (int k = tid; k < EMB_; k += 256) {
    float val = emb[tok * EMB_ + k];
    half hi = __float2half(val);
    g_x_hi[k * B_ + b] = hi;
    g_x_lo[k * B_ + b] = __float2half(val - __half2float(hi));
  }
}

// ---------------- host ----------------
extern "C" void kernel_launch(void* const* d_in, const int* in_sizes, int n_in,
                              void* d_out, int out_size) {
  const float* z     = (const float*)d_in[0];
  const float* emb   = (const float*)d_in[1];
  const float* w_ih  = (const float*)d_in[2];
  const float* w_hh  = (const float*)d_in[3];
  const float* bias  = (const float*)d_in[4];
  const float* w_out = (const float*)d_in[5];
  const float* b_out = (const float*)d_in[6];
  const int*   sid   = (n_in > 7) ? (const int*)d_in[7] : nullptr;

  float* out  = (float*)d_out;
  float* outS = out;
  float* outP = out + B_ * T_;
  if (out_size == B_ * T_ * V_) { outS = nullptr; outP = out; }

  k_conv_comb<<<512, 256>>>(w_ih, w_hh);
  k_conv_wout<<<2048, 256>>>(w_out);
  k_init<<<(H_ * B_ + 255) / 256, 256>>>(z, sid, emb);

  for (int t = 0; t < T_; ++t) {
    uint32_t fk0, fk1;
    tf2x32(0u, 42u, 0u, (uint32_t)t, fk0, fk1);   // fold_in(key(42), t)
    k_gates<<<dim3(GROWS / RB, KSPL), 256>>>();
    k_cell<<<(H_ * B_ + 255) / 256, 256>>>(bias);
    k_logits<<<V_ / RB, 256>>>();
    k_sample_part<<<dim3(NCH, B_), 256>>>(b_out, fk0, fk1);
    k_post<<<dim3(NPB + 1, B_), 256>>>(w_out, b_out, emb, outS, outP, t, fk0, fk1);
  }
}

// round 5
// speedup vs baseline: 4.1940x; 1.5519x over previous
#include <cuda_runtime.h>
#include <cuda_fp16.h>
#include <mma.h>
#include <cstdint>
#include <math.h>

using namespace nvcuda;

#define B_    32
#define V_    32000
#define EMB_  512
#define H_    1024
#define T_    100
#define KG    2048
#define GROWS 4096
#define KSPL  8              // split-K for gates (virtual K = 4096)
#define GRB   64             // gates rows/block
#define LRB   64             // logits rows/block
#define NBLK  (V_ / LRB)     // 500 logits blocks
#define KC    32
#define NPB   16             // p-writer blocks per batch row
#define VCH   (V_ / NPB)     // 2000
#define DELTA 0.05f

// ---------------- static device state ----------------
__device__ __align__(128) half  g_wc_hi[GROWS * KG];
__device__ __align__(128) half  g_wc_lo[GROWS * KG];
__device__ __align__(128) half  g_wo[(size_t)V_ * H_];
__device__ __align__(128) half  g_x_hi[KG * B_];
__device__ __align__(128) half  g_x_lo[KG * B_];
__device__ __align__(128) float g_part[(size_t)KSPL * GROWS * B_];
__device__ __align__(128) float g_logits[B_ * V_];   // stores logit + b_out
__device__ __align__(128) float g_c[H_ * B_];
__device__ __align__(128) float g_hf[B_ * H_];
__device__ int    g_s[B_];
__device__ float4 g_cA2[B_ * NBLK];   // (chunk max, chunk sum, top1 val, top1 idx-bits)
__device__ float2 g_cB2[B_ * NBLK];   // (top2 val, top2 idx-bits)

// ---------------- cp.async helpers ----------------
__device__ __forceinline__ void cp16(void* sdst, const void* gsrc) {
  uint32_t d = (uint32_t)__cvta_generic_to_shared(sdst);
  asm volatile("cp.async.cg.shared.global [%0], [%1], 16;\n" :: "r"(d), "l"(gsrc));
}
#define CP_COMMIT() asm volatile("cp.async.commit_group;\n" ::: "memory")
#define CP_WAIT(n)  asm volatile("cp.async.wait_group %0;\n" :: "n"(n) : "memory")

// ---------------- threefry2x32 (exact JAX, partitionable) ----------------
__host__ __device__ inline void tf2x32(uint32_t k0, uint32_t k1, uint32_t x0, uint32_t x1,
                                       uint32_t &o0, uint32_t &o1) {
  uint32_t ks2 = k0 ^ k1 ^ 0x1BD11BDAu;
  x0 += k0; x1 += k1;
#define TF_R(r) do { x0 += x1; x1 = (x1 << (r)) | (x1 >> (32 - (r))); x1 ^= x0; } while (0)
  TF_R(13); TF_R(15); TF_R(26); TF_R(6);
  x0 += k1;  x1 += ks2 + 1u;
  TF_R(17); TF_R(29); TF_R(16); TF_R(24);
  x0 += ks2; x1 += k0 + 2u;
  TF_R(13); TF_R(15); TF_R(26); TF_R(6);
  x0 += k0;  x1 += k1 + 3u;
  TF_R(17); TF_R(29); TF_R(16); TF_R(24);
  x0 += k1;  x1 += ks2 + 4u;
  TF_R(13); TF_R(15); TF_R(26); TF_R(6);
  x0 += ks2; x1 += k0 + 5u;
#undef TF_R
  o0 = x0; o1 = x1;
}

__device__ __forceinline__ float gumbel_of(uint32_t k0, uint32_t k1, uint32_t i) {
  uint32_t a, b;
  tf2x32(k0, k1, 0u, i, a, b);
  uint32_t bits = a ^ b;
  float u = __uint_as_float((bits >> 9) | 0x3f800000u) - 1.0f;
  const float tiny = 1.17549435e-38f;
  float val = fmaxf(tiny, u * (1.0f - tiny) + tiny);
  return -logf(-logf(val));
}

__device__ __forceinline__ float sigm(float x) { return 1.0f / (1.0f + expf(-x)); }

// top-2 merge helper (value desc, index asc tie-break)
__device__ __forceinline__ void merge2(float &v1, int &i1, float &v2, int &i2,
                                       float b1, int j1, float b2, int j2) {
  float n1, n2; int m1, m2;
  bool bf = (b1 > v1) || (b1 == v1 && j1 < i1);
  if (bf) { n1 = b1; m1 = j1; bool tk = (v1 > b2) || (v1 == b2 && i1 < j2);
            n2 = tk ? v1 : b2; m2 = tk ? i1 : j2; }
  else    { n1 = v1; m1 = i1; bool tk = (b1 > v2) || (b1 == v2 && j1 < i2);
            n2 = tk ? b1 : v2; m2 = tk ? j1 : i2; }
  v1 = n1; i1 = m1; v2 = n2; i2 = m2;
}

// ---------------- conversion / init ----------------
__global__ void k_conv_comb(const float* __restrict__ w_ih, const float* __restrict__ w_hh) {
  for (int i = blockIdx.x * blockDim.x + threadIdx.x; i < GROWS * KG; i += gridDim.x * blockDim.x) {
    int r = i >> 11, k = i & 2047;
    float v = (k < 1024) ? __ldcs(w_ih + r * 1024 + k) : __ldcs(w_hh + r * 1024 + (k - 1024));
    half hi = __float2half(v);
    g_wc_hi[i] = hi;
    g_wc_lo[i] = __float2half(v - __half2float(hi));
  }
}
__global__ void k_conv_wout(const float* __restrict__ w) {
  for (size_t i = blockIdx.x * blockDim.x + threadIdx.x; i < (size_t)V_ * H_;
       i += (size_t)gridDim.x * blockDim.x)
    g_wo[i] = __float2half(__ldcs(w + i));
}
__global__ void k_init(const float* __restrict__ z, const int* __restrict__ sid,
                       const float* __restrict__ emb) {
  int idx = blockIdx.x * blockDim.x + threadIdx.x;
  if (idx < H_ * B_) {
    g_c[idx] = 0.0f;
    g_x_hi[H_ * B_ + idx] = __float2half(0.0f);
    g_x_lo[H_ * B_ + idx] = __float2half(0.0f);
    int b = idx & 31, hid = idx >> 5;
    g_hf[b * H_ + hid] = 0.0f;
  }
  if (idx < EMB_ * B_) {
    int b = idx & 31, k = idx >> 5;
    float v = z[b * EMB_ + k];
    half hi = __float2half(v);
    g_x_hi[(EMB_ + k) * B_ + b] = hi;
    g_x_lo[(EMB_ + k) * B_ + b] = __float2half(v - __half2float(hi));
    int tok = sid ? sid[0] : 0;
    float e = emb[tok * EMB_ + k];
    half ehi = __float2half(e);
    g_x_hi[k * B_ + b] = ehi;
    g_x_lo[k * B_ + b] = __float2half(e - __half2float(ehi));
  }
  if (idx < B_) g_s[idx] = sid ? sid[0] : 0;
}

// ---------------- gates GEMM.  grid (64, 8), block 128 (4 warps x 16 rows) ---
__global__ void k_gates() {
  __shared__ half As[3][GRB * 40];
  __shared__ half Bh[3][KC * 40];
  __shared__ half Bl[3][KC * 40];
  const int row0 = blockIdx.x * GRB;
  const int ks = blockIdx.y;
  const int tid = threadIdx.x, w = tid >> 5;
  const bool hiPhase = ks < 4;
  const half* Wsrc = hiPhase ? g_wc_hi : g_wc_lo;
  const int kk0 = (ks & 3) * 512;
  const int NCHK = 512 / KC;   // 16

  wmma::fragment<wmma::accumulator, 16, 16, 16, float> fc0, fc1;
  wmma::fill_fragment(fc0, 0.0f); wmma::fill_fragment(fc1, 0.0f);

  auto issue = [&](int c) {
    int s = c % 3, kk = kk0 + c * KC;
#pragma unroll
    for (int j = 0; j < 2; j++) {
      int idx = tid + 128 * j, r = idx >> 2, cc = idx & 3;
      cp16(&As[s][r * 40 + cc * 8], Wsrc + (size_t)(row0 + r) * KG + kk + cc * 8);
    }
    {
      int r = tid >> 2, cc = tid & 3;
      cp16(&Bh[s][r * 40 + cc * 8], g_x_hi + (kk + r) * B_ + cc * 8);
      if (hiPhase)
        cp16(&Bl[s][r * 40 + cc * 8], g_x_lo + (kk + r) * B_ + cc * 8);
    }
    CP_COMMIT();
  };

  issue(0); issue(1); issue(2);

  for (int c = 0; c < NCHK; c++) {
    if (c + 3 < NCHK) { CP_WAIT(2); } else { CP_WAIT(0); }
    __syncthreads();
    int s = c % 3;
    wmma::fragment<wmma::matrix_a, 16, 16, 16, half, wmma::row_major> fa;
    wmma::fragment<wmma::matrix_b, 16, 16, 16, half, wmma::row_major> fb0, fb1;
#pragma unroll
    for (int k4 = 0; k4 < 2; k4++) {
      wmma::load_matrix_sync(fa, &As[s][(w * 16) * 40 + k4 * 16], 40);
      wmma::load_matrix_sync(fb0, &Bh[s][(k4 * 16) * 40 + 0], 40);
      wmma::load_matrix_sync(fb1, &Bh[s][(k4 * 16) * 40 + 16], 40);
      wmma::mma_sync(fc0, fa, fb0, fc0);
      wmma::mma_sync(fc1, fa, fb1, fc1);
      if (hiPhase) {
        wmma::load_matrix_sync(fb0, &Bl[s][(k4 * 16) * 40 + 0], 40);
        wmma::load_matrix_sync(fb1, &Bl[s][(k4 * 16) * 40 + 16], 40);
        wmma::mma_sync(fc0, fa, fb0, fc0);
        wmma::mma_sync(fc1, fa, fb1, fc1);
      }
    }
    __syncthreads();
    if (c + 3 < NCHK) issue(c + 3);
  }
  float* dst = g_part + ((size_t)ks * GROWS + row0 + w * 16) * B_;
  wmma::store_matrix_sync(dst, fc0, B_, wmma::mem_row_major);
  wmma::store_matrix_sync(dst + 16, fc1, B_, wmma::mem_row_major);
}

// ---------------- LSTM cell (+ split-K reduce) ----------------
__global__ void k_cell(const float* __restrict__ bias) {
  int idx = blockIdx.x * blockDim.x + threadIdx.x;
  if (idx >= H_ * B_) return;
  int b = idx & 31, hid = idx >> 5;
  float ig = 0.f, fg = 0.f, gg = 0.f, og = 0.f;
#pragma unroll
  for (int ks = 0; ks < KSPL; ks++) {
    const float* p = g_part + (size_t)ks * GROWS * B_;
    ig += p[hid * B_ + b];
    fg += p[(H_ + hid) * B_ + b];
    gg += p[(2 * H_ + hid) * B_ + b];
    og += p[(3 * H_ + hid) * B_ + b];
  }
  ig += bias[hid]; fg += bias[H_ + hid]; gg += bias[2 * H_ + hid]; og += bias[3 * H_ + hid];
  float c  = g_c[idx];
  float cn = sigm(fg) * c + sigm(ig) * tanhf(gg);
  float hn = sigm(og) * tanhf(cn);
  g_c[idx] = cn;
  g_hf[b * H_ + hid] = hn;
  half hi = __float2half(hn);
  g_x_hi[(H_ + hid) * B_ + b] = hi;
  g_x_lo[(H_ + hid) * B_ + b] = __float2half(hn - __half2float(hi));
}

// ------- logits GEMM + fused sampling stats.  grid 500, block 128 ------------
__global__ void k_logits(const float* __restrict__ bout, uint32_t k0, uint32_t k1) {
  __shared__ half  As[3][LRB * 40];
  __shared__ half  Bs[3][KC * 40];
  __shared__ float Ls[LRB * 36];
  const int blk = blockIdx.x;
  const int row0 = blk * LRB;
  const int tid = threadIdx.x, w = tid >> 5;
  const half* Bsrc = g_x_hi + H_ * B_;
  const int NCHK = H_ / KC;   // 32

  wmma::fragment<wmma::accumulator, 16, 16, 16, float> fc0, fc1;
  wmma::fill_fragment(fc0, 0.0f); wmma::fill_fragment(fc1, 0.0f);

  auto issue = [&](int c) {
    int s = c % 3, kk = c * KC;
#pragma unroll
    for (int j = 0; j < 2; j++) {
      int idx = tid + 128 * j, r = idx >> 2, cc = idx & 3;
      cp16(&As[s][r * 40 + cc * 8], g_wo + (size_t)(row0 + r) * H_ + kk + cc * 8);
    }
    {
      int r = tid >> 2, cc = tid & 3;
      cp16(&Bs[s][r * 40 + cc * 8], Bsrc + (kk + r) * B_ + cc * 8);
    }
    CP_COMMIT();
  };

  issue(0); issue(1); issue(2);

  for (int c = 0; c < NCHK; c++) {
    if (c + 3 < NCHK) { CP_WAIT(2); } else { CP_WAIT(0); }
    __syncthreads();
    int s = c % 3;
    wmma::fragment<wmma::matrix_a, 16, 16, 16, half, wmma::row_major> fa;
    wmma::fragment<wmma::matrix_b, 16, 16, 16, half, wmma::row_major> fb0, fb1;
#pragma unroll
    for (int k4 = 0; k4 < 2; k4++) {
      wmma::load_matrix_sync(fa, &As[s][(w * 16) * 40 + k4 * 16], 40);
      wmma::load_matrix_sync(fb0, &Bs[s][(k4 * 16) * 40 + 0], 40);
      wmma::load_matrix_sync(fb1, &Bs[s][(k4 * 16) * 40 + 16], 40);
      wmma::mma_sync(fc0, fa, fb0, fc0);
      wmma::mma_sync(fc1, fa, fb1, fc1);
    }
    __syncthreads();
    if (c + 3 < NCHK) issue(c + 3);
  }

  // epilogue: stage to smem (rows x 32 cols, row-major ld 36)
  wmma::store_matrix_sync(&Ls[(w * 16) * 36 + 0],  fc0, 36, wmma::mem_row_major);
  wmma::store_matrix_sync(&Ls[(w * 16) * 36 + 16], fc1, 36, wmma::mem_row_major);
  __syncthreads();

  // add bias, write logits+bout to global (coalesced)
  for (int i = tid; i < LRB * B_; i += 128) {
    int b = i >> 6, r = i & 63;
    float lb = Ls[r * 36 + b] + bout[row0 + r];
    Ls[r * 36 + b] = lb;
    g_logits[b * V_ + row0 + r] = lb;
  }
  __syncthreads();

  // per-column stats: c = batch, 4 threads per column
  int c = tid >> 2, sub = tid & 3;
  float m = -INFINITY, s = 0.0f, v1 = -INFINITY, v2 = -INFINITY;
  int i1 = 0x7fffffff, i2 = 0x7fffffff;
  for (int r = sub; r < LRB; r += 4) {
    float lb = Ls[r * 36 + c];
    if (lb > m) { s = s * expf(m - lb) + 1.0f; m = lb; } else s += expf(lb - m);
    int v = row0 + r;
    float tv = lb + gumbel_of(k0, k1, (uint32_t)(c * V_ + v));
    if (tv > v1 || (tv == v1 && v < i1)) { v2 = v1; i2 = i1; v1 = tv; i1 = v; }
    else if (tv > v2 || (tv == v2 && v < i2)) { v2 = tv; i2 = v; }
  }
#pragma unroll
  for (int o = 1; o <= 2; o <<= 1) {
    float om = __shfl_xor_sync(0xffffffffu, m, o);
    float os = __shfl_xor_sync(0xffffffffu, s, o);
    float M = fmaxf(m, om);
    s = s * expf(m - M) + os * expf(om - M); m = M;
    float b1 = __shfl_xor_sync(0xffffffffu, v1, o);
    int   j1 = __shfl_xor_sync(0xffffffffu, i1, o);
    float b2 = __shfl_xor_sync(0xffffffffu, v2, o);
    int   j2 = __shfl_xor_sync(0xffffffffu, i2, o);
    merge2(v1, i1, v2, i2, b1, j1, b2, j2);
  }
  if (sub == 0) {
    g_cA2[c * NBLK + blk] = make_float4(m, s, v1, __int_as_float(i1));
    g_cB2[c * NBLK + blk] = make_float2(v2, __int_as_float(i2));
  }
}

// ---- post: reduce chunk stats; p write (blocks 0..15); finalize (block 16) ---
__global__ void k_post(const float* __restrict__ wout, const float* __restrict__ bout,
                       const float* __restrict__ emb,
                       float* outS, float* __restrict__ outP,
                       int t, uint32_t k0, uint32_t k1) {
  int c = blockIdx.x, b = blockIdx.y, tid = threadIdx.x;
  __shared__ float rm[256], rs[256], r1[256], r2[256];
  __shared__ int   q1[256], q2[256];
  float m = -INFINITY, s = 0.0f, v1 = -INFINITY, v2 = -INFINITY;
  int i1 = 0x7fffffff, i2 = 0x7fffffff;
  for (int j = tid; j < NBLK; j += 256) {
    float4 a = g_cA2[b * NBLK + j];
    float2 e = g_cB2[b * NBLK + j];
    float M = fmaxf(m, a.x);
    s = s * expf(m - M) + a.y * expf(a.x - M); m = M;
    merge2(v1, i1, v2, i2, a.z, __float_as_int(a.w), e.x, __float_as_int(e.y));
  }
  rm[tid] = m; rs[tid] = s; r1[tid] = v1; r2[tid] = v2; q1[tid] = i1; q2[tid] = i2;
  __syncthreads();
  for (int off = 128; off; off >>= 1) {
    if (tid < off) {
      float mA = rm[tid], mB = rm[tid + off];
      float M = fmaxf(mA, mB);
      rm[tid] = M;
      rs[tid] = rs[tid] * expf(mA - M) + rs[tid + off] * expf(mB - M);
      float a1 = r1[tid], a2 = r2[tid]; int x1 = q1[tid], x2 = q2[tid];
      merge2(a1, x1, a2, x2, r1[tid + off], q1[tid + off], r2[tid + off], q2[tid + off]);
      r1[tid] = a1; r2[tid] = a2; q1[tid] = x1; q2[tid] = x2;
    }
    __syncthreads();
  }
  float gm = rm[0], ginv = 1.0f / rs[0], gtop = r1[0];
  __syncthreads();

  if (c < NPB) {
    int vbeg = c * VCH;
    float* op = outP + ((size_t)b * T_ + t) * V_;
    for (int v = vbeg + tid; v < vbeg + VCH; v += 256)
      __stcs(op + v, expf(g_logits[b * V_ + v] - gm) * ginv);
    return;
  }

  // finalize: collect candidates within DELTA of approx winner
  __shared__ int ncand;
  __shared__ int cands[64];
  __shared__ double cval[64];
  __shared__ int    cidx[64];
  __shared__ int    s_tok;
  if (tid == 0) ncand = 0;
  __syncthreads();
  float thr = gtop - DELTA;
  for (int j = tid; j < NBLK; j += 256) {
    float4 a = g_cA2[b * NBLK + j];
    float2 e = g_cB2[b * NBLK + j];
    if (a.z >= thr) { int p = atomicAdd(&ncand, 1); if (p < 64) cands[p] = __float_as_int(a.w); }
    if (e.x >= thr) { int p = atomicAdd(&ncand, 1); if (p < 64) cands[p] = __float_as_int(e.y); }
  }
  __syncthreads();
  int n = ncand < 64 ? ncand : 64;
  int w = tid >> 5, lane = tid & 31;
  for (int ci = w; ci < n; ci += 8) {
    int v = cands[ci];
    const float* wr = wout + (size_t)v * H_;
    const float* hr = g_hf + b * H_;
    double acc = 0.0;
    for (int j = lane; j < H_; j += 32) acc += (double)wr[j] * (double)hr[j];
    for (int o = 16; o; o >>= 1) acc += __shfl_down_sync(0xffffffffu, acc, o);
    if (lane == 0) {
      cval[ci] = acc + (double)bout[v] + (double)gumbel_of(k0, k1, (uint32_t)(b * V_ + v));
      cidx[ci] = v;
    }
  }
  __syncthreads();
  if (tid == 0) {
    double bv = -1e300; int bi = 0x7fffffff;
    for (int ci = 0; ci < n; ci++)
      if (cval[ci] > bv || (cval[ci] == bv && cidx[ci] < bi)) { bv = cval[ci]; bi = cidx[ci]; }
    s_tok = bi;
    g_s[b] = bi;
    if (outS) outS[b * T_ + t] = (float)bi;
  }
  __syncthreads();
  int tok = s_tok;
  for (int k = tid; k < EMB_; k += 256) {
    float val = emb[tok * EMB_ + k];
    half hi = __float2half(val);
    g_x_hi[k * B_ + b] = hi;
    g_x_lo[k * B_ + b] = __float2half(val - __half2float(hi));
  }
}

// ---------------- host ----------------
extern "C" void kernel_launch(void* const* d_in, const int* in_sizes, int n_in,
                              void* d_out, int out_size) {
  const float* z     = (const float*)d_in[0];
  const float* emb   = (const float*)d_in[1];
  const float* w_ih  = (const float*)d_in[2];
  const float* w_hh  = (const float*)d_in[3];
  const float* bias  = (const float*)d_in[4];
  const float* w_out = (const float*)d_in[5];
  const float* b_out = (const float*)d_in[6];
  const int*   sid   = (n_in > 7) ? (const int*)d_in[7] : nullptr;

  float* out  = (float*)d_out;
  float* outS = out;
  float* outP = out + B_ * T_;
  if (out_size == B_ * T_ * V_) { outS = nullptr; outP = out; }

  k_conv_comb<<<512, 256>>>(w_ih, w_hh);
  k_conv_wout<<<2048, 256>>>(w_out);
  k_init<<<(H_ * B_ + 255) / 256, 256>>>(z, sid, emb);

  for (int t = 0; t < T_; ++t) {
    uint32_t fk0, fk1;
    tf2x32(0u, 42u, 0u, (uint32_t)t, fk0, fk1);   // fold_in(key(42), t)
    k_gates<<<dim3(GROWS / GRB, KSPL), 128>>>();
    k_cell<<<(H_ * B_ + 255) / 256, 256>>>(bias);
    k_logits<<<NBLK, 128>>>(b_out, fk0, fk1);
    k_post<<<dim3(NPB + 1, B_), 256>>>(w_out, b_out, emb, outS, outP, t, fk0, fk1);
  }
}

// round 6
// speedup vs baseline: 4.3448x; 1.0359x over previous
#include <cuda_runtime.h>
#include <cuda_fp16.h>
#include <mma.h>
#include <cstdint>
#include <math.h>

using namespace nvcuda;

#define B_    32
#define V_    32000
#define EMB_  512
#define H_    1024
#define T_    100
#define KG    2048
#define GROWS 4096
#define KSPL  8
#define GRB   64
#define LRB   64
#define NBLK  (V_ / LRB)     // 500
#define KC    32
#define NPB   16
#define VCH   (V_ / NPB)
#define DELTA 0.05f

// ---------------- static device state ----------------
__device__ __align__(128) half  g_wc_hi[GROWS * KG];
__device__ __align__(128) half  g_wc_lo[GROWS * KG];
__device__ __align__(128) half  g_wo[(size_t)V_ * H_];
__device__ __align__(128) half  g_x_hi[KG * B_];
__device__ __align__(128) half  g_x_lo[KG * B_];
__device__ __align__(128) float g_part[(size_t)KSPL * GROWS * B_];
__device__ __align__(128) float g_logits[B_ * V_];
__device__ __align__(128) float g_c[H_ * B_];
__device__ __align__(128) float g_hf[B_ * H_];
__device__ int    g_s[B_];
__device__ float2 g_cM[B_ * NBLK];    // (chunk max, chunk sumexp)
__device__ float4 g_cT[B_ * NBLK];    // (top1 val, top1 idx, top2 val, top2 idx)

// ---------------- L2 policy + async-copy helpers ----------------
__device__ __forceinline__ uint64_t pol_last() {
  uint64_t p;
  asm("createpolicy.fractional.L2::evict_last.b64 %0, 1.0;" : "=l"(p));
  return p;
}
__device__ __forceinline__ void cp16p(void* sdst, const void* gsrc, uint64_t pol) {
  uint32_t d = (uint32_t)__cvta_generic_to_shared(sdst);
  asm volatile("cp.async.cg.shared.global.L2::cache_hint [%0], [%1], 16, %2;\n"
               :: "r"(d), "l"(gsrc), "l"(pol));
}
__device__ __forceinline__ void st32p(void* gdst, uint32_t v, uint64_t pol) {
  asm volatile("st.global.L2::cache_hint.b32 [%0], %1, %2;\n" :: "l"(gdst), "r"(v), "l"(pol));
}
#define CP_COMMIT() asm volatile("cp.async.commit_group;\n" ::: "memory")
#define CP_WAIT(n)  asm volatile("cp.async.wait_group %0;\n" :: "n"(n) : "memory")

// ---------------- threefry2x32 (exact JAX, partitionable) ----------------
__host__ __device__ inline void tf2x32(uint32_t k0, uint32_t k1, uint32_t x0, uint32_t x1,
                                       uint32_t &o0, uint32_t &o1) {
  uint32_t ks2 = k0 ^ k1 ^ 0x1BD11BDAu;
  x0 += k0; x1 += k1;
#define TF_R(r) do { x0 += x1; x1 = (x1 << (r)) | (x1 >> (32 - (r))); x1 ^= x0; } while (0)
  TF_R(13); TF_R(15); TF_R(26); TF_R(6);
  x0 += k1;  x1 += ks2 + 1u;
  TF_R(17); TF_R(29); TF_R(16); TF_R(24);
  x0 += ks2; x1 += k0 + 2u;
  TF_R(13); TF_R(15); TF_R(26); TF_R(6);
  x0 += k0;  x1 += k1 + 3u;
  TF_R(17); TF_R(29); TF_R(16); TF_R(24);
  x0 += k1;  x1 += ks2 + 4u;
  TF_R(13); TF_R(15); TF_R(26); TF_R(6);
  x0 += ks2; x1 += k0 + 5u;
#undef TF_R
  o0 = x0; o1 = x1;
}

__device__ __forceinline__ float gumbel_of(uint32_t k0, uint32_t k1, uint32_t i) {
  uint32_t a, b;
  tf2x32(k0, k1, 0u, i, a, b);
  uint32_t bits = a ^ b;
  float u = __uint_as_float((bits >> 9) | 0x3f800000u) - 1.0f;
  const float tiny = 1.17549435e-38f;
  float val = fmaxf(tiny, u * (1.0f - tiny) + tiny);
  return -logf(-logf(val));
}

__device__ __forceinline__ float sigm(float x) { return 1.0f / (1.0f + expf(-x)); }

__device__ __forceinline__ void merge2(float &v1, int &i1, float &v2, int &i2,
                                       float b1, int j1, float b2, int j2) {
  float n1, n2; int m1, m2;
  bool bf = (b1 > v1) || (b1 == v1 && j1 < i1);
  if (bf) { n1 = b1; m1 = j1; bool tk = (v1 > b2) || (v1 == b2 && i1 < j2);
            n2 = tk ? v1 : b2; m2 = tk ? i1 : j2; }
  else    { n1 = v1; m1 = i1; bool tk = (b1 > v2) || (b1 == v2 && j1 < i2);
            n2 = tk ? b1 : v2; m2 = tk ? j1 : i2; }
  v1 = n1; i1 = m1; v2 = n2; i2 = m2;
}

// ---------------- conversion (weights born L2-resident) ----------------
__global__ void k_conv_comb(const float* __restrict__ w_ih, const float* __restrict__ w_hh) {
  uint64_t pol = pol_last();
  int np = GROWS * KG / 2;
  for (int p = blockIdx.x * blockDim.x + threadIdx.x; p < np; p += gridDim.x * blockDim.x) {
    int r = p >> 10, kp = (p & 1023) * 2;
    float v0, v1;
    if (kp < 1024) { v0 = __ldcs(w_ih + r * 1024 + kp); v1 = __ldcs(w_ih + r * 1024 + kp + 1); }
    else           { v0 = __ldcs(w_hh + r * 1024 + kp - 1024); v1 = __ldcs(w_hh + r * 1024 + kp - 1023); }
    half h0 = __float2half(v0), h1 = __float2half(v1);
    half2 hi = __halves2half2(h0, h1);
    half2 lo = __halves2half2(__float2half(v0 - __half2float(h0)),
                              __float2half(v1 - __half2float(h1)));
    size_t off = (size_t)r * KG + kp;
    st32p(&g_wc_hi[off], *(uint32_t*)&hi, pol);
    st32p(&g_wc_lo[off], *(uint32_t*)&lo, pol);
  }
}
__global__ void k_conv_wout(const float* __restrict__ w) {
  uint64_t pol = pol_last();
  size_t np = (size_t)V_ * H_ / 2;
  for (size_t p = blockIdx.x * blockDim.x + threadIdx.x; p < np; p += (size_t)gridDim.x * blockDim.x) {
    float v0 = __ldcs(w + 2 * p), v1 = __ldcs(w + 2 * p + 1);
    half2 h = __halves2half2(__float2half(v0), __float2half(v1));
    st32p(&g_wo[2 * p], *(uint32_t*)&h, pol);
  }
}
__global__ void k_init(const float* __restrict__ z, const int* __restrict__ sid,
                       const float* __restrict__ emb) {
  int idx = blockIdx.x * blockDim.x + threadIdx.x;
  if (idx < H_ * B_) {
    g_c[idx] = 0.0f;
    g_x_hi[H_ * B_ + idx] = __float2half(0.0f);
    g_x_lo[H_ * B_ + idx] = __float2half(0.0f);
    int b = idx & 31, hid = idx >> 5;
    g_hf[b * H_ + hid] = 0.0f;
  }
  if (idx < EMB_ * B_) {
    int b = idx & 31, k = idx >> 5;
    float v = z[b * EMB_ + k];
    half hi = __float2half(v);
    g_x_hi[(EMB_ + k) * B_ + b] = hi;
    g_x_lo[(EMB_ + k) * B_ + b] = __float2half(v - __half2float(hi));
    int tok = sid ? sid[0] : 0;
    float e = emb[tok * EMB_ + k];
    half ehi = __float2half(e);
    g_x_hi[k * B_ + b] = ehi;
    g_x_lo[k * B_ + b] = __float2half(e - __half2float(ehi));
  }
  if (idx < B_) g_s[idx] = sid ? sid[0] : 0;
}

// ---------------- gates GEMM.  grid (64, 8), block 128, 4-stage cp.async -----
__global__ void k_gates() {
  __shared__ half As[4][GRB * 40];
  __shared__ half Bh[4][KC * 40];
  __shared__ half Bl[4][KC * 40];
  const int row0 = blockIdx.x * GRB;
  const int ks = blockIdx.y;
  const int tid = threadIdx.x, w = tid >> 5;
  const bool hiPhase = ks < 4;
  const half* Wsrc = hiPhase ? g_wc_hi : g_wc_lo;
  const int kk0 = (ks & 3) * 512;
  const int NCHK = 512 / KC;   // 16
  uint64_t pol = pol_last();

  wmma::fragment<wmma::accumulator, 16, 16, 16, float> fc0, fc1;
  wmma::fill_fragment(fc0, 0.0f); wmma::fill_fragment(fc1, 0.0f);

  auto issue = [&](int c) {
    int s = c & 3, kk = kk0 + c * KC;
#pragma unroll
    for (int j = 0; j < 2; j++) {
      int idx = tid + 128 * j, r = idx >> 2, cc = idx & 3;
      cp16p(&As[s][r * 40 + cc * 8], Wsrc + (size_t)(row0 + r) * KG + kk + cc * 8, pol);
    }
    {
      int r = tid >> 2, cc = tid & 3;
      cp16p(&Bh[s][r * 40 + cc * 8], g_x_hi + (kk + r) * B_ + cc * 8, pol);
      if (hiPhase)
        cp16p(&Bl[s][r * 40 + cc * 8], g_x_lo + (kk + r) * B_ + cc * 8, pol);
    }
    CP_COMMIT();
  };

  issue(0); issue(1); issue(2);

  for (int c = 0; c < NCHK; c++) {
    if (c + 3 < NCHK) { CP_WAIT(2); } else { CP_WAIT(0); }
    __syncthreads();
    int s = c & 3;
    wmma::fragment<wmma::matrix_a, 16, 16, 16, half, wmma::row_major> fa;
    wmma::fragment<wmma::matrix_b, 16, 16, 16, half, wmma::row_major> fb0, fb1;
#pragma unroll
    for (int k4 = 0; k4 < 2; k4++) {
      wmma::load_matrix_sync(fa, &As[s][(w * 16) * 40 + k4 * 16], 40);
      wmma::load_matrix_sync(fb0, &Bh[s][(k4 * 16) * 40 + 0], 40);
      wmma::load_matrix_sync(fb1, &Bh[s][(k4 * 16) * 40 + 16], 40);
      wmma::mma_sync(fc0, fa, fb0, fc0);
      wmma::mma_sync(fc1, fa, fb1, fc1);
      if (hiPhase) {
        wmma::load_matrix_sync(fb0, &Bl[s][(k4 * 16) * 40 + 0], 40);
        wmma::load_matrix_sync(fb1, &Bl[s][(k4 * 16) * 40 + 16], 40);
        wmma::mma_sync(fc0, fa, fb0, fc0);
        wmma::mma_sync(fc1, fa, fb1, fc1);
      }
    }
    __syncthreads();
    if (c + 3 < NCHK) issue(c + 3);
  }
  float* dst = g_part + ((size_t)ks * GROWS + row0 + w * 16) * B_;
  wmma::store_matrix_sync(dst, fc0, B_, wmma::mem_row_major);
  wmma::store_matrix_sync(dst + 16, fc1, B_, wmma::mem_row_major);
}

// ---------------- LSTM cell (+ split-K reduce) ----------------
__global__ void k_cell(const float* __restrict__ bias) {
  int idx = blockIdx.x * blockDim.x + threadIdx.x;
  if (idx >= H_ * B_) return;
  int b = idx & 31, hid = idx >> 5;
  float ig = 0.f, fg = 0.f, gg = 0.f, og = 0.f;
#pragma unroll
  for (int ks = 0; ks < KSPL; ks++) {
    const float* p = g_part + (size_t)ks * GROWS * B_;
    ig += __ldcs(p + hid * B_ + b);
    fg += __ldcs(p + (H_ + hid) * B_ + b);
    gg += __ldcs(p + (2 * H_ + hid) * B_ + b);
    og += __ldcs(p + (3 * H_ + hid) * B_ + b);
  }
  ig += bias[hid]; fg += bias[H_ + hid]; gg += bias[2 * H_ + hid]; og += bias[3 * H_ + hid];
  float c  = g_c[idx];
  float cn = sigm(fg) * c + sigm(ig) * tanhf(gg);
  float hn = sigm(og) * tanhf(cn);
  g_c[idx] = cn;
  g_hf[b * H_ + hid] = hn;
  half hi = __float2half(hn);
  g_x_hi[(H_ + hid) * B_ + b] = hi;
  g_x_lo[(H_ + hid) * B_ + b] = __float2half(hn - __half2float(hi));
}

// ------- logits GEMM + fused sampling stats.  grid 500, block 128 ------------
__global__ void k_logits(const float* __restrict__ bout, uint32_t k0, uint32_t k1) {
  __shared__ half  As[4][LRB * 40];
  __shared__ half  Bs[4][KC * 40];
  __shared__ float Ls[LRB * 36];
  const int blk = blockIdx.x;
  const int row0 = blk * LRB;
  const int tid = threadIdx.x, w = tid >> 5;
  const half* Bsrc = g_x_hi + H_ * B_;
  const int NCHK = H_ / KC;   // 32
  uint64_t pol = pol_last();

  wmma::fragment<wmma::accumulator, 16, 16, 16, float> fc0, fc1;
  wmma::fill_fragment(fc0, 0.0f); wmma::fill_fragment(fc1, 0.0f);

  auto issue = [&](int c) {
    int s = c & 3, kk = c * KC;
#pragma unroll
    for (int j = 0; j < 2; j++) {
      int idx = tid + 128 * j, r = idx >> 2, cc = idx & 3;
      cp16p(&As[s][r * 40 + cc * 8], g_wo + (size_t)(row0 + r) * H_ + kk + cc * 8, pol);
    }
    {
      int r = tid >> 2, cc = tid & 3;
      cp16p(&Bs[s][r * 40 + cc * 8], Bsrc + (kk + r) * B_ + cc * 8, pol);
    }
    CP_COMMIT();
  };

  issue(0); issue(1); issue(2);

  for (int c = 0; c < NCHK; c++) {
    if (c + 3 < NCHK) { CP_WAIT(2); } else { CP_WAIT(0); }
    __syncthreads();
    int s = c & 3;
    wmma::fragment<wmma::matrix_a, 16, 16, 16, half, wmma::row_major> fa;
    wmma::fragment<wmma::matrix_b, 16, 16, 16, half, wmma::row_major> fb0, fb1;
#pragma unroll
    for (int k4 = 0; k4 < 2; k4++) {
      wmma::load_matrix_sync(fa, &As[s][(w * 16) * 40 + k4 * 16], 40);
      wmma::load_matrix_sync(fb0, &Bs[s][(k4 * 16) * 40 + 0], 40);
      wmma::load_matrix_sync(fb1, &Bs[s][(k4 * 16) * 40 + 16], 40);
      wmma::mma_sync(fc0, fa, fb0, fc0);
      wmma::mma_sync(fc1, fa, fb1, fc1);
    }
    __syncthreads();
    if (c + 3 < NCHK) issue(c + 3);
  }

  wmma::store_matrix_sync(&Ls[(w * 16) * 36 + 0],  fc0, 36, wmma::mem_row_major);
  wmma::store_matrix_sync(&Ls[(w * 16) * 36 + 16], fc1, 36, wmma::mem_row_major);
  __syncthreads();

  for (int i = tid; i < LRB * B_; i += 128) {
    int b = i >> 6, r = i & 63;
    float lb = Ls[r * 36 + b] + bout[row0 + r];
    Ls[r * 36 + b] = lb;
    __stcs(&g_logits[b * V_ + row0 + r], lb);
  }
  __syncthreads();

  int c = tid >> 2, sub = tid & 3;
  float m = -INFINITY, s = 0.0f, v1 = -INFINITY, v2 = -INFINITY;
  int i1 = 0x7fffffff, i2 = 0x7fffffff;
  for (int r = sub; r < LRB; r += 4) {
    float lb = Ls[r * 36 + c];
    if (lb > m) { s = s * expf(m - lb) + 1.0f; m = lb; } else s += expf(lb - m);
    int v = row0 + r;
    float tv = lb + gumbel_of(k0, k1, (uint32_t)(c * V_ + v));
    if (tv > v1 || (tv == v1 && v < i1)) { v2 = v1; i2 = i1; v1 = tv; i1 = v; }
    else if (tv > v2 || (tv == v2 && v < i2)) { v2 = tv; i2 = v; }
  }
#pragma unroll
  for (int o = 1; o <= 2; o <<= 1) {
    float om = __shfl_xor_sync(0xffffffffu, m, o);
    float os = __shfl_xor_sync(0xffffffffu, s, o);
    float M = fmaxf(m, om);
    s = s * expf(m - M) + os * expf(om - M); m = M;
    float b1 = __shfl_xor_sync(0xffffffffu, v1, o);
    int   j1 = __shfl_xor_sync(0xffffffffu, i1, o);
    float b2 = __shfl_xor_sync(0xffffffffu, v2, o);
    int   j2 = __shfl_xor_sync(0xffffffffu, i2, o);
    merge2(v1, i1, v2, i2, b1, j1, b2, j2);
  }
  if (sub == 0) {
    g_cM[c * NBLK + blk] = make_float2(m, s);
    g_cT[c * NBLK + blk] = make_float4(v1, __int_as_float(i1), v2, __int_as_float(i2));
  }
}

// ---- post: p write (blocks 0..15) + finalize (block 16).  grid (17,32) -------
__global__ void k_post(const float* __restrict__ wout, const float* __restrict__ bout,
                       const float* __restrict__ emb,
                       float* outS, float* __restrict__ outP,
                       int t, uint32_t k0, uint32_t k1) {
  int c = blockIdx.x, b = blockIdx.y, tid = threadIdx.x;
  __shared__ float rm[256], rs[256];
  float m = -INFINITY, s = 0.0f;
  for (int j = tid; j < NBLK; j += 256) {
    float2 a = g_cM[b * NBLK + j];
    float M = fmaxf(m, a.x);
    s = s * expf(m - M) + a.y * expf(a.x - M); m = M;
  }
  rm[tid] = m; rs[tid] = s;
  __syncthreads();
  for (int off = 128; off; off >>= 1) {
    if (tid < off) {
      float mA = rm[tid], mB = rm[tid + off];
      float M = fmaxf(mA, mB);
      rm[tid] = M;
      rs[tid] = rs[tid] * expf(mA - M) + rs[tid + off] * expf(mB - M);
    }
    __syncthreads();
  }
  float gm = rm[0], ginv = 1.0f / rs[0];
  __syncthreads();

  if (c < NPB) {
    int vbeg = c * VCH;
    float* op = outP + ((size_t)b * T_ + t) * V_;
    for (int v = vbeg + tid; v < vbeg + VCH; v += 256)
      __stcs(op + v, expf(__ldcs(&g_logits[b * V_ + v]) - gm) * ginv);
    return;
  }

  // finalize: global top-1 of approx (l+g), then exact recompute of near-ties
  __shared__ float r1[256];
  __shared__ int   q1[256];
  float v1 = -INFINITY; int i1 = 0x7fffffff;
  for (int j = tid; j < NBLK; j += 256) {
    float4 a = g_cT[b * NBLK + j];
    float dummy2 = -INFINITY; int dummyi = 0x7fffffff;
    merge2(v1, i1, dummy2, dummyi, a.x, __float_as_int(a.y), a.z, __float_as_int(a.w));
  }
  r1[tid] = v1; q1[tid] = i1;
  __syncthreads();
  for (int off = 128; off; off >>= 1) {
    if (tid < off) {
      float bv = r1[tid + off]; int bi = q1[tid + off];
      if (bv > r1[tid] || (bv == r1[tid] && bi < q1[tid])) { r1[tid] = bv; q1[tid] = bi; }
    }
    __syncthreads();
  }
  float gtop = r1[0];
  __syncthreads();

  __shared__ int ncand;
  __shared__ int cands[64];
  __shared__ double cval[64];
  __shared__ int    cidx[64];
  __shared__ int    s_tok;
  if (tid == 0) ncand = 0;
  __syncthreads();
  float thr = gtop - DELTA;
  for (int j = tid; j < NBLK; j += 256) {
    float4 a = g_cT[b * NBLK + j];
    if (a.x >= thr) { int p = atomicAdd(&ncand, 1); if (p < 64) cands[p] = __float_as_int(a.y); }
    if (a.z >= thr) { int p = atomicAdd(&ncand, 1); if (p < 64) cands[p] = __float_as_int(a.w); }
  }
  __syncthreads();
  int n = ncand < 64 ? ncand : 64;
  int w = tid >> 5, lane = tid & 31;
  for (int ci = w; ci < n; ci += 8) {
    int v = cands[ci];
    const float* wr = wout + (size_t)v * H_;
    const float* hr = g_hf + b * H_;
    double acc = 0.0;
    for (int j = lane; j < H_; j += 32) acc += (double)__ldcs(wr + j) * (double)hr[j];
    for (int o = 16; o; o >>= 1) acc += __shfl_down_sync(0xffffffffu, acc, o);
    if (lane == 0) {
      cval[ci] = acc + (double)bout[v] + (double)gumbel_of(k0, k1, (uint32_t)(b * V_ + v));
      cidx[ci] = v;
    }
  }
  __syncthreads();
  if (tid == 0) {
    double bv = -1e300; int bi = 0x7fffffff;
    for (int ci = 0; ci < n; ci++)
      if (cval[ci] > bv || (cval[ci] == bv && cidx[ci] < bi)) { bv = cval[ci]; bi = cidx[ci]; }
    s_tok = bi;
    g_s[b] = bi;
    if (outS) outS[b * T_ + t] = (float)bi;
  }
  __syncthreads();
  int tok = s_tok;
  for (int k = tid; k < EMB_; k += 256) {
    float val = emb[tok * EMB_ + k];
    half hi = __float2half(val);
    g_x_hi[k * B_ + b] = hi;
    g_x_lo[k * B_ + b] = __float2half(val - __half2float(hi));
  }
}

// ---------------- host ----------------
extern "C" void kernel_launch(void* const* d_in, const int* in_sizes, int n_in,
                              void* d_out, int out_size) {
  const float* z     = (const float*)d_in[0];
  const float* emb   = (const float*)d_in[1];
  const float* w_ih  = (const float*)d_in[2];
  const float* w_hh  = (const float*)d_in[3];
  const float* bias  = (const float*)d_in[4];
  const float* w_out = (const float*)d_in[5];
  const float* b_out = (const float*)d_in[6];
  const int*   sid   = (n_in > 7) ? (const int*)d_in[7] : nullptr;

  float* out  = (float*)d_out;
  float* outS = out;
  float* outP = out + B_ * T_;
  if (out_size == B_ * T_ * V_) { outS = nullptr; outP = out; }

  k_conv_comb<<<512, 256>>>(w_ih, w_hh);
  k_conv_wout<<<2048, 256>>>(w_out);
  k_init<<<(H_ * B_ + 255) / 256, 256>>>(z, sid, emb);

  for (int t = 0; t < T_; ++t) {
    uint32_t fk0, fk1;
    tf2x32(0u, 42u, 0u, (uint32_t)t, fk0, fk1);
    k_gates<<<dim3(GROWS / GRB, KSPL), 128>>>();
    k_cell<<<(H_ * B_ + 255) / 256, 256>>>(bias);
    k_logits<<<NBLK, 128>>>(b_out, fk0, fk1);
    k_post<<<dim3(NPB + 1, B_), 256>>>(w_out, b_out, emb, outS, outP, t, fk0, fk1);
  }
}